// round 1
// baseline (speedup 1.0000x reference)
#include <cuda_runtime.h>
#include <cuda_bf16.h>
#include <cstdint>

#define NN 32000
#define EE 512000
#define ET (EE + NN)           // edges + self loops
#define DD 128
#define HH 4
#define EAD 16

// ---------------- scratch (device globals; no runtime alloc) ----------------
__device__ int   g_is64;
__device__ int   g_deg[NN];
__device__ int   g_off[NN + 1];
__device__ int   g_cur[NN];
__device__ int   g_csrc[ET];

__device__ float g_h1[(size_t)NN * 512];   // x @ W1            (64MB)
__device__ float g_e1[(size_t)NN * 512];   // elu(agg1 + b1)    (64MB)
__device__ float g_att1s[NN * 4];
__device__ float g_att1d[NN * 4];
__device__ float g_h2[(size_t)NN * 128];   // e1 @ W2
__device__ float g_t [(size_t)NN * 128];   // elu(agg2 + b2)
__device__ float g_u [(size_t)NN * 128];   // relu(t@Wo1+bo1)
__device__ float g_att2s[NN];
__device__ float g_att2d[NN];
__device__ float g_P[(size_t)NN * 128];    // xo @ We1[0:128]   + be1
__device__ float g_Q[(size_t)NN * 128];    // xo @ We1[128:256]

// ---------------- helpers ----------------
__device__ __forceinline__ float lrelu02(float a) { return a > 0.f ? a : 0.2f * a; }
__device__ __forceinline__ float eluf(float v)    { return v > 0.f ? v : expm1f(v); }

__device__ __forceinline__ int idx_at(const void* ei, long pos, int is64) {
    if (is64) return (int)((const long long*)ei)[pos];
    return ((const int*)ei)[pos];
}

// ---------------- dtype detector: int64 edge_index has zero high words ----------------
__global__ void k_detect(const int* w) {
    __shared__ int s_any;
    if (threadIdx.x == 0) s_any = 0;
    __syncthreads();
    int any = 0;
    for (int i = threadIdx.x; i < 1024; i += blockDim.x) any |= w[2 * i + 1];
    if (any) atomicOr(&s_any, 1);
    __syncthreads();
    if (threadIdx.x == 0) g_is64 = (s_any == 0) ? 1 : 0;
}

__global__ void k_zero_deg() {
    int i = blockIdx.x * blockDim.x + threadIdx.x;
    if (i < NN) g_deg[i] = 0;
}

__global__ void k_hist(const void* ei) {
    int is64 = g_is64;
    long e = (long)blockIdx.x * blockDim.x + threadIdx.x;
    if (e >= ET) return;
    int d = (e < EE) ? idx_at(ei, (long)EE + e, is64) : (int)(e - EE);
    atomicAdd(&g_deg[d], 1);
}

__global__ void k_scan() {   // 1 block, 1024 threads
    __shared__ int part[1024];
    const int tid = threadIdx.x;
    const int per = 32;                  // 1024*32 >= NN
    int base = tid * per;
    int sum = 0;
    for (int i = 0; i < per; i++) {
        int idx = base + i;
        if (idx < NN) sum += g_deg[idx];
    }
    part[tid] = sum;
    __syncthreads();
    for (int off = 1; off < 1024; off <<= 1) {
        int v = 0;
        if (tid >= off) v = part[tid - off];
        __syncthreads();
        part[tid] += v;
        __syncthreads();
    }
    int run = (tid == 0) ? 0 : part[tid - 1];
    for (int i = 0; i < per; i++) {
        int idx = base + i;
        if (idx < NN) {
            g_off[idx] = run;
            g_cur[idx] = run;
            run += g_deg[idx];
        }
    }
    if (tid == 1023) g_off[NN] = part[1023];
}

__global__ void k_scatter(const void* ei) {
    int is64 = g_is64;
    long e = (long)blockIdx.x * blockDim.x + threadIdx.x;
    if (e >= ET) return;
    int s, d;
    if (e < EE) {
        s = idx_at(ei, e, is64);
        d = idx_at(ei, (long)EE + e, is64);
    } else {
        s = d = (int)(e - EE);
    }
    int pos = atomicAdd(&g_cur[d], 1);
    g_csrc[pos] = s;
}

// ---------------- generic fp32 SGEMM: C = act(A[M,K] @ B[K,Nn] + bias) ----------------
// BM=BN=128, BK=8, 256 threads, 8x8 per thread. M,Nn multiples of 128; K multiple of 8.
template <int ACT>  // 0 none, 1 relu
__device__ __forceinline__ void sgemm_body(const float* __restrict__ A,
                                           const float* __restrict__ B,
                                           const float* __restrict__ bias,
                                           float* __restrict__ C,
                                           int M, int Nn, int K) {
    __shared__ float As[8][128];
    __shared__ float Bs[8][128];
    const int tid = threadIdx.x;
    const int tx = tid & 15, ty = tid >> 4;
    const int row0 = blockIdx.y * 128, col0 = blockIdx.x * 128;
    float acc[8][8];
#pragma unroll
    for (int i = 0; i < 8; i++)
#pragma unroll
        for (int j = 0; j < 8; j++) acc[i][j] = 0.f;

    const int arow = tid >> 1, ak4 = (tid & 1) * 4;
    const int bcol = tid & 127, bk0 = tid >> 7;

    for (int k0 = 0; k0 < K; k0 += 8) {
        float4 av = *(const float4*)&A[(size_t)(row0 + arow) * K + k0 + ak4];
        As[ak4 + 0][arow] = av.x;
        As[ak4 + 1][arow] = av.y;
        As[ak4 + 2][arow] = av.z;
        As[ak4 + 3][arow] = av.w;
#pragma unroll
        for (int i = 0; i < 4; i++)
            Bs[bk0 + 2 * i][bcol] = B[(size_t)(k0 + bk0 + 2 * i) * Nn + col0 + bcol];
        __syncthreads();
#pragma unroll
        for (int kk = 0; kk < 8; kk++) {
            float a[8], b[8];
            float4 a0 = *(const float4*)&As[kk][ty * 8];
            float4 a1 = *(const float4*)&As[kk][ty * 8 + 4];
            float4 b0 = *(const float4*)&Bs[kk][tx * 8];
            float4 b1 = *(const float4*)&Bs[kk][tx * 8 + 4];
            a[0] = a0.x; a[1] = a0.y; a[2] = a0.z; a[3] = a0.w;
            a[4] = a1.x; a[5] = a1.y; a[6] = a1.z; a[7] = a1.w;
            b[0] = b0.x; b[1] = b0.y; b[2] = b0.z; b[3] = b0.w;
            b[4] = b1.x; b[5] = b1.y; b[6] = b1.z; b[7] = b1.w;
#pragma unroll
            for (int i = 0; i < 8; i++)
#pragma unroll
                for (int j = 0; j < 8; j++) acc[i][j] += a[i] * b[j];
        }
        __syncthreads();
    }
#pragma unroll
    for (int i = 0; i < 8; i++) {
        size_t r = row0 + ty * 8 + i;
#pragma unroll
        for (int h = 0; h < 2; h++) {
            int c = col0 + tx * 8 + h * 4;
            float4 v;
            v.x = acc[i][h * 4 + 0];
            v.y = acc[i][h * 4 + 1];
            v.z = acc[i][h * 4 + 2];
            v.w = acc[i][h * 4 + 3];
            if (bias) {
                float4 bv = *(const float4*)&bias[c];
                v.x += bv.x; v.y += bv.y; v.z += bv.z; v.w += bv.w;
            }
            if (ACT == 1) {
                v.x = fmaxf(v.x, 0.f); v.y = fmaxf(v.y, 0.f);
                v.z = fmaxf(v.z, 0.f); v.w = fmaxf(v.w, 0.f);
            }
            *(float4*)&C[r * Nn + c] = v;
        }
    }
}

__global__ void __launch_bounds__(256) k_gemm1(const float* x, const float* W1) {
    sgemm_body<0>(x, W1, nullptr, g_h1, NN, 512, 128);
}
__global__ void __launch_bounds__(256) k_gemm2(const float* W2) {
    sgemm_body<0>(g_e1, W2, nullptr, g_h2, NN, 128, 512);
}
__global__ void __launch_bounds__(256) k_gemm3(const float* Wo1, const float* bo1) {
    sgemm_body<1>(g_t, Wo1, bo1, g_u, NN, 128, 128);
}
__global__ void __launch_bounds__(256) k_gemm4(const float* Wo2, const float* bo2, float* xo) {
    sgemm_body<0>(g_u, Wo2, bo2, xo, NN, 128, 128);
}
__global__ void __launch_bounds__(256) k_gemmP(const float* xo, const float* We1, const float* be1) {
    sgemm_body<0>(xo, We1, be1, g_P, NN, 128, 128);
}
__global__ void __launch_bounds__(256) k_gemmQ(const float* xo, const float* We1) {
    sgemm_body<0>(xo, We1 + 128 * 128, nullptr, g_Q, NN, 128, 128);
}

// ---------------- attention dot products (warp per node) ----------------
__device__ __forceinline__ void att_body(const float* __restrict__ hmat,
                                         const float* __restrict__ a_s,
                                         const float* __restrict__ a_d,
                                         float* __restrict__ outs,
                                         float* __restrict__ outd, int heads) {
    int gw = (int)((blockIdx.x * blockDim.x + threadIdx.x) >> 5);
    int lane = threadIdx.x & 31;
    if (gw >= NN) return;
    int hd = heads * 128;
    for (int h = 0; h < heads; h++) {
        float4 hv = *(const float4*)&hmat[(size_t)gw * hd + h * 128 + lane * 4];
        float4 vs = *(const float4*)&a_s[h * 128 + lane * 4];
        float4 vd = *(const float4*)&a_d[h * 128 + lane * 4];
        float ss = hv.x * vs.x + hv.y * vs.y + hv.z * vs.z + hv.w * vs.w;
        float sd = hv.x * vd.x + hv.y * vd.y + hv.z * vd.z + hv.w * vd.w;
#pragma unroll
        for (int off = 16; off; off >>= 1) {
            ss += __shfl_xor_sync(0xffffffffu, ss, off);
            sd += __shfl_xor_sync(0xffffffffu, sd, off);
        }
        if (lane == 0) {
            outs[gw * heads + h] = ss;
            outd[gw * heads + h] = sd;
        }
    }
}
__global__ void k_att1(const float* a_s, const float* a_d) {
    att_body(g_h1, a_s, a_d, g_att1s, g_att1d, 4);
}
__global__ void k_att2(const float* a_s, const float* a_d) {
    att_body(g_h2, a_s, a_d, g_att2s, g_att2d, 1);
}

// ---------------- layer-1 aggregation: block per dst node, 128 threads ----------------
__global__ void __launch_bounds__(128) k_agg1(const float* __restrict__ b1) {
    const int n = blockIdx.x, tid = threadIdx.x;
    const int lane = tid & 31;
    const int h = tid >> 5;                 // head for my 4 channels (tid*4 .. tid*4+3)
    const int beg = g_off[n], end = g_off[n + 1];

    __shared__ float sden[4];
    __shared__ float s_ex[128 * 4];
    __shared__ int   s_s[128];
    if (tid < 4) sden[tid] = 0.f;
    __syncthreads();

    const float4 ad = *(const float4*)&g_att1d[n * 4];

    // pass 1: softmax denominators (no max subtraction needed: |alpha| small)
    float d0 = 0.f, d1 = 0.f, d2 = 0.f, d3 = 0.f;
    for (int i = beg + tid; i < end; i += 128) {
        int s = g_csrc[i];
        float4 as = *(const float4*)&g_att1s[s * 4];
        d0 += expf(lrelu02(as.x + ad.x));
        d1 += expf(lrelu02(as.y + ad.y));
        d2 += expf(lrelu02(as.z + ad.z));
        d3 += expf(lrelu02(as.w + ad.w));
    }
#pragma unroll
    for (int off = 16; off; off >>= 1) {
        d0 += __shfl_xor_sync(0xffffffffu, d0, off);
        d1 += __shfl_xor_sync(0xffffffffu, d1, off);
        d2 += __shfl_xor_sync(0xffffffffu, d2, off);
        d3 += __shfl_xor_sync(0xffffffffu, d3, off);
    }
    if (lane == 0) {
        atomicAdd(&sden[0], d0);
        atomicAdd(&sden[1], d1);
        atomicAdd(&sden[2], d2);
        atomicAdd(&sden[3], d3);
    }
    __syncthreads();
    const float invden = 1.f / sden[h];

    // pass 2: weighted sum of h1[src] rows
    float4 acc = make_float4(0.f, 0.f, 0.f, 0.f);
    for (int c0 = beg; c0 < end; c0 += 128) {
        int m = min(128, end - c0);
        if (tid < m) {
            int s = g_csrc[c0 + tid];
            s_s[tid] = s;
            float4 as = *(const float4*)&g_att1s[s * 4];
            s_ex[tid * 4 + 0] = expf(lrelu02(as.x + ad.x));
            s_ex[tid * 4 + 1] = expf(lrelu02(as.y + ad.y));
            s_ex[tid * 4 + 2] = expf(lrelu02(as.z + ad.z));
            s_ex[tid * 4 + 3] = expf(lrelu02(as.w + ad.w));
        }
        __syncthreads();
        for (int j = 0; j < m; j++) {
            float w = s_ex[j * 4 + h] * invden;
            float4 hv = *(const float4*)&g_h1[(size_t)s_s[j] * 512 + tid * 4];
            acc.x += hv.x * w; acc.y += hv.y * w;
            acc.z += hv.z * w; acc.w += hv.w * w;
        }
        __syncthreads();
    }
    float4 bv = *(const float4*)&b1[tid * 4];
    float4 o;
    o.x = eluf(acc.x + bv.x); o.y = eluf(acc.y + bv.y);
    o.z = eluf(acc.z + bv.z); o.w = eluf(acc.w + bv.w);
    *(float4*)&g_e1[(size_t)n * 512 + tid * 4] = o;
}

// ---------------- layer-2 aggregation (1 head, 128 channels) ----------------
__global__ void __launch_bounds__(128) k_agg2(const float* __restrict__ b2) {
    const int n = blockIdx.x, tid = threadIdx.x;
    const int lane = tid & 31;
    const int beg = g_off[n], end = g_off[n + 1];

    __shared__ float sden;
    __shared__ float s_ex[128];
    __shared__ int   s_s[128];
    if (tid == 0) sden = 0.f;
    __syncthreads();

    const float adn = g_att2d[n];

    float dsum = 0.f;
    for (int i = beg + tid; i < end; i += 128)
        dsum += expf(lrelu02(g_att2s[g_csrc[i]] + adn));
#pragma unroll
    for (int off = 16; off; off >>= 1) dsum += __shfl_xor_sync(0xffffffffu, dsum, off);
    if (lane == 0) atomicAdd(&sden, dsum);
    __syncthreads();
    const float invden = 1.f / sden;

    float acc = 0.f;
    for (int c0 = beg; c0 < end; c0 += 128) {
        int m = min(128, end - c0);
        if (tid < m) {
            int s = g_csrc[c0 + tid];
            s_s[tid] = s;
            s_ex[tid] = expf(lrelu02(g_att2s[s] + adn));
        }
        __syncthreads();
        for (int j = 0; j < m; j++) {
            float w = s_ex[j] * invden;
            acc += g_h2[(size_t)s_s[j] * 128 + tid] * w;
        }
        __syncthreads();
    }
    g_t[(size_t)n * 128 + tid] = eluf(acc + b2[tid]);
}

// ---------------- fused edge MLP: hidden = relu(P[s]+Q[d]+ea@We1_ea); out = hidden@We2+be2 ----------------
__global__ void __launch_bounds__(256) k_edge_final(const void* __restrict__ ei,
                                                    const float* __restrict__ eattr,
                                                    const float* __restrict__ We1,
                                                    const float* __restrict__ We2,
                                                    const float* __restrict__ be2,
                                                    float* __restrict__ out) {
    __shared__ float sW1[16 * 128];     // We1 rows 256..271
    __shared__ float sW2[128 * 16];
    __shared__ float sHid[8][128];
    const int tid = threadIdx.x;
    for (int i = tid; i < 2048; i += 256) {
        sW1[i] = We1[256 * 128 + i];
        sW2[i] = We2[i];
    }
    const int is64 = g_is64;
    __syncthreads();

    const int warp = tid >> 5, lane = tid & 31;
    const long e = (long)blockIdx.x * 8 + warp;
    if (e < EE) {
        int s = idx_at(ei, e, is64);
        int d = idx_at(ei, (long)EE + e, is64);
        float4 p = *(const float4*)&g_P[(size_t)s * 128 + lane * 4];
        float4 q = *(const float4*)&g_Q[(size_t)d * 128 + lane * 4];
        float4 hv;
        hv.x = p.x + q.x; hv.y = p.y + q.y; hv.z = p.z + q.z; hv.w = p.w + q.w;
        float eav = (lane < 16) ? eattr[e * 16 + lane] : 0.f;
#pragma unroll
        for (int k = 0; k < 16; k++) {
            float ek = __shfl_sync(0xffffffffu, eav, k);
            float4 wv = *(const float4*)&sW1[k * 128 + lane * 4];
            hv.x += ek * wv.x; hv.y += ek * wv.y;
            hv.z += ek * wv.z; hv.w += ek * wv.w;
        }
        hv.x = fmaxf(hv.x, 0.f); hv.y = fmaxf(hv.y, 0.f);
        hv.z = fmaxf(hv.z, 0.f); hv.w = fmaxf(hv.w, 0.f);
        *(float4*)&sHid[warp][lane * 4] = hv;
    }
    __syncwarp();
    if (e < EE) {
        const int o = lane & 15, half = lane >> 4;
        float acc = 0.f;
#pragma unroll
        for (int c = 0; c < 64; c++) {
            int cc = half * 64 + c;
            acc += sHid[warp][cc] * sW2[cc * 16 + o];
        }
        acc += __shfl_xor_sync(0xffffffffu, acc, 16);
        if (lane < 16) out[e * 16 + lane] = acc + be2[lane];
    }
}

// ---------------- launcher ----------------
extern "C" void kernel_launch(void* const* d_in, const int* in_sizes, int n_in,
                              void* d_out, int out_size) {
    const float* x    = (const float*)d_in[0];
    const void*  ei   = d_in[1];
    const float* eatt = (const float*)d_in[2];
    const float* W1   = (const float*)d_in[3];
    const float* as1  = (const float*)d_in[4];
    const float* ad1  = (const float*)d_in[5];
    const float* b1   = (const float*)d_in[6];
    const float* W2   = (const float*)d_in[7];
    const float* as2  = (const float*)d_in[8];
    const float* ad2  = (const float*)d_in[9];
    const float* b2   = (const float*)d_in[10];
    const float* Wo1  = (const float*)d_in[11];
    const float* bo1  = (const float*)d_in[12];
    const float* Wo2  = (const float*)d_in[13];
    const float* bo2  = (const float*)d_in[14];
    const float* We1  = (const float*)d_in[15];
    const float* be1  = (const float*)d_in[16];
    const float* We2  = (const float*)d_in[17];
    const float* be2  = (const float*)d_in[18];

    float* out  = (float*)d_out;
    float* xo   = out;                          // [NN,128]
    float* eout = out + (size_t)NN * 128;       // [EE,16]

    // CSR build (by dst, self-loops appended)
    k_detect<<<1, 256>>>((const int*)ei);
    k_zero_deg<<<(NN + 255) / 256, 256>>>();
    k_hist<<<(ET + 255) / 256, 256>>>(ei);
    k_scan<<<1, 1024>>>();
    k_scatter<<<(ET + 255) / 256, 256>>>(ei);

    // layer 1
    k_gemm1<<<dim3(4, 250), 256>>>(x, W1);
    k_att1<<<4000, 256>>>(as1, ad1);
    k_agg1<<<NN, 128>>>(b1);

    // layer 2
    k_gemm2<<<dim3(1, 250), 256>>>(W2);
    k_att2<<<4000, 256>>>(as2, ad2);
    k_agg2<<<NN, 128>>>(b2);

    // output MLP -> xo
    k_gemm3<<<dim3(1, 250), 256>>>(Wo1, bo1);
    k_gemm4<<<dim3(1, 250), 256>>>(Wo2, bo2, xo);

    // edge MLP decomposition: P = xo@We1[0:128]+be1, Q = xo@We1[128:256]
    k_gemmP<<<dim3(1, 250), 256>>>(xo, We1, be1);
    k_gemmQ<<<dim3(1, 250), 256>>>(xo, We1);
    k_edge_final<<<EE / 8, 256>>>(ei, eatt, We1, We2, be2, eout);
}

// round 2
// speedup vs baseline: 1.0992x; 1.0992x over previous
#include <cuda_runtime.h>
#include <cuda_bf16.h>
#include <cstdint>

#define NN 32000
#define EE 512000
#define ET (EE + NN)           // edges + self loops
#define DD 128
#define HH 4
#define EAD 16

typedef unsigned long long u64;

// ---------------- scratch (device globals; no runtime alloc) ----------------
__device__ int   g_is64;
__device__ int   g_deg[NN];
__device__ int   g_off[NN + 1];
__device__ int   g_cur[NN];
__device__ int   g_csrc[ET];
__device__ int   g_bsum[128];
__device__ int   g_boff[128];

__device__ float g_h1[(size_t)NN * 512];   // x @ W1            (64MB)
__device__ float g_e1[(size_t)NN * 512];   // elu(agg1 + b1)    (64MB)
__device__ float g_att1s[NN * 4];
__device__ float g_att1d[NN * 4];
__device__ float g_h2[(size_t)NN * 128];   // e1 @ W2
__device__ float g_t [(size_t)NN * 128];   // elu(agg2 + b2)
__device__ float g_u [(size_t)NN * 128];   // relu(t@Wo1+bo1)
__device__ float g_att2s[NN];
__device__ float g_att2d[NN];
__device__ float g_P[(size_t)NN * 128];    // xo @ We1[0:128]   + be1
__device__ float g_Q[(size_t)NN * 128];    // xo @ We1[128:256]

// ---------------- helpers ----------------
__device__ __forceinline__ float lrelu02(float a) { return a > 0.f ? a : 0.2f * a; }
__device__ __forceinline__ float eluf(float v)    { return v > 0.f ? v : expm1f(v); }

__device__ __forceinline__ int idx_at(const void* ei, long pos, int is64) {
    if (is64) return (int)((const long long*)ei)[pos];
    return ((const int*)ei)[pos];
}

__device__ __forceinline__ u64 pack2(float x) {
    u64 r; asm("mov.b64 %0, {%1, %1};" : "=l"(r) : "f"(x)); return r;
}
__device__ __forceinline__ void fma2(u64 &d, u64 a, u64 b) {
    asm("fma.rn.f32x2 %0, %1, %2, %0;" : "+l"(d) : "l"(a), "l"(b));
}
__device__ __forceinline__ float2 unpack2(u64 p) {
    float2 v; asm("mov.b64 {%0, %1}, %2;" : "=f"(v.x), "=f"(v.y) : "l"(p)); return v;
}

// ---------------- dtype detector: int64 edge_index has zero high words ----------------
__global__ void k_detect(const int* w) {
    __shared__ int s_any;
    if (threadIdx.x == 0) s_any = 0;
    __syncthreads();
    int any = 0;
    for (int i = threadIdx.x; i < 1024; i += blockDim.x) any |= w[2 * i + 1];
    if (any) atomicOr(&s_any, 1);
    __syncthreads();
    if (threadIdx.x == 0) g_is64 = (s_any == 0) ? 1 : 0;
}

__global__ void k_zero_deg() {
    int i = blockIdx.x * blockDim.x + threadIdx.x;
    if (i < NN) g_deg[i] = 0;
}

__global__ void k_hist(const void* ei) {
    int is64 = g_is64;
    long e = (long)blockIdx.x * blockDim.x + threadIdx.x;
    if (e >= ET) return;
    int d = (e < EE) ? idx_at(ei, (long)EE + e, is64) : (int)(e - EE);
    atomicAdd(&g_deg[d], 1);
}

// ---------------- hierarchical scan: 125 blocks x 256 = 32000 exactly ----------------
__global__ void k_scan1() {
    __shared__ int s[256];
    const int tid = threadIdx.x;
    const int idx = blockIdx.x * 256 + tid;
    int v = g_deg[idx];
    s[tid] = v;
    __syncthreads();
#pragma unroll
    for (int off = 1; off < 256; off <<= 1) {
        int t = (tid >= off) ? s[tid - off] : 0;
        __syncthreads();
        s[tid] += t;
        __syncthreads();
    }
    g_off[idx] = s[tid] - v;            // exclusive within block
    if (tid == 255) g_bsum[blockIdx.x] = s[255];
}

__global__ void k_scan2() {             // 1 block, 128 threads
    __shared__ int s[128];
    const int tid = threadIdx.x;
    int v = (tid < 125) ? g_bsum[tid] : 0;
    s[tid] = v;
    __syncthreads();
#pragma unroll
    for (int off = 1; off < 128; off <<= 1) {
        int t = (tid >= off) ? s[tid - off] : 0;
        __syncthreads();
        s[tid] += t;
        __syncthreads();
    }
    if (tid < 125) g_boff[tid] = s[tid] - v;
    if (tid == 127) g_off[NN] = s[127];
}

__global__ void k_scan3() {
    const int idx = blockIdx.x * 256 + threadIdx.x;
    int o = g_off[idx] + g_boff[blockIdx.x];
    g_off[idx] = o;
    g_cur[idx] = o;
}

__global__ void k_scatter(const void* ei) {
    int is64 = g_is64;
    long e = (long)blockIdx.x * blockDim.x + threadIdx.x;
    if (e >= ET) return;
    int s, d;
    if (e < EE) {
        s = idx_at(ei, e, is64);
        d = idx_at(ei, (long)EE + e, is64);
    } else {
        s = d = (int)(e - EE);
    }
    int pos = atomicAdd(&g_cur[d], 1);
    g_csrc[pos] = s;
}

// ---------------- FFMA2 SGEMM: C = act(A[M,K] @ B[K,Nn] + bias) ----------------
// 128x128 tile, BK=16, 256 threads, 8x8 per thread (as 8x4 f32x2 pairs),
// double-buffered smem with register prefetch.
// ATTH: 0 none; 1 fused attention dots, head=0; 2 fused attention dots, head=blockIdx.x
template <int ACT, int ATTH>
__device__ __forceinline__ void sgemm_core(const float* __restrict__ A,
                                           const float* __restrict__ B,
                                           const float* __restrict__ bias,
                                           float* __restrict__ C,
                                           int M, int Nn, int K,
                                           const float* __restrict__ a_s,
                                           const float* __restrict__ a_d,
                                           float* __restrict__ atts,
                                           float* __restrict__ attd,
                                           int heads) {
    __shared__ float As[2][16][132];    // transposed: As[buf][k][m]
    __shared__ float Bs[2][16][128];
    const int tid = threadIdx.x;
    const int tx = tid & 15, ty = tid >> 4;
    const int row0 = blockIdx.y * 128, col0 = blockIdx.x * 128;

    // A loads: thread -> row (tid&127), col-octet ((tid>>7)*8)
    const int arow = tid & 127;
    const int ac8  = (tid >> 7) * 8;
    // B loads: thread -> 2 consecutive float4 in 16x128 tile
    const int bi   = tid * 2;
    const int brow = bi >> 5;
    const int bcol = (bi & 31) * 4;

    const float* Aptr = A + (size_t)(row0 + arow) * K + ac8;
    const float* Bptr = B + (size_t)brow * Nn + col0 + bcol;

    u64 acc[8][4];
#pragma unroll
    for (int i = 0; i < 8; i++)
#pragma unroll
        for (int j = 0; j < 4; j++) acc[i][j] = 0ull;

    // prefetch tile 0
    float4 pa0 = *(const float4*)(Aptr + 0);
    float4 pa1 = *(const float4*)(Aptr + 4);
    float4 pb0 = *(const float4*)(Bptr + 0);
    float4 pb1 = *(const float4*)(Bptr + 4);

    // store tile 0
    As[0][ac8 + 0][arow] = pa0.x; As[0][ac8 + 1][arow] = pa0.y;
    As[0][ac8 + 2][arow] = pa0.z; As[0][ac8 + 3][arow] = pa0.w;
    As[0][ac8 + 4][arow] = pa1.x; As[0][ac8 + 5][arow] = pa1.y;
    As[0][ac8 + 6][arow] = pa1.z; As[0][ac8 + 7][arow] = pa1.w;
    *(float4*)&Bs[0][brow][bcol]     = pb0;
    *(float4*)&Bs[0][brow][bcol + 4] = pb1;
    __syncthreads();

    int buf = 0;
    for (int k0 = 16;; k0 += 16) {
        const bool more = (k0 < K);
        if (more) {
            pa0 = *(const float4*)(Aptr + k0);
            pa1 = *(const float4*)(Aptr + k0 + 4);
            pb0 = *(const float4*)(Bptr + (size_t)k0 * Nn);
            pb1 = *(const float4*)(Bptr + (size_t)k0 * Nn + 4);
        }
#pragma unroll
        for (int kk = 0; kk < 16; kk++) {
            float4 a0 = *(const float4*)&As[buf][kk][ty * 8];
            float4 a1 = *(const float4*)&As[buf][kk][ty * 8 + 4];
            const u64* bp = (const u64*)&Bs[buf][kk][tx * 8];
            u64 b0 = bp[0], b1 = bp[1], b2 = bp[2], b3 = bp[3];
            u64 ap;
            ap = pack2(a0.x); fma2(acc[0][0], ap, b0); fma2(acc[0][1], ap, b1); fma2(acc[0][2], ap, b2); fma2(acc[0][3], ap, b3);
            ap = pack2(a0.y); fma2(acc[1][0], ap, b0); fma2(acc[1][1], ap, b1); fma2(acc[1][2], ap, b2); fma2(acc[1][3], ap, b3);
            ap = pack2(a0.z); fma2(acc[2][0], ap, b0); fma2(acc[2][1], ap, b1); fma2(acc[2][2], ap, b2); fma2(acc[2][3], ap, b3);
            ap = pack2(a0.w); fma2(acc[3][0], ap, b0); fma2(acc[3][1], ap, b1); fma2(acc[3][2], ap, b2); fma2(acc[3][3], ap, b3);
            ap = pack2(a1.x); fma2(acc[4][0], ap, b0); fma2(acc[4][1], ap, b1); fma2(acc[4][2], ap, b2); fma2(acc[4][3], ap, b3);
            ap = pack2(a1.y); fma2(acc[5][0], ap, b0); fma2(acc[5][1], ap, b1); fma2(acc[5][2], ap, b2); fma2(acc[5][3], ap, b3);
            ap = pack2(a1.z); fma2(acc[6][0], ap, b0); fma2(acc[6][1], ap, b1); fma2(acc[6][2], ap, b2); fma2(acc[6][3], ap, b3);
            ap = pack2(a1.w); fma2(acc[7][0], ap, b0); fma2(acc[7][1], ap, b1); fma2(acc[7][2], ap, b2); fma2(acc[7][3], ap, b3);
        }
        if (!more) break;
        buf ^= 1;
        As[buf][ac8 + 0][arow] = pa0.x; As[buf][ac8 + 1][arow] = pa0.y;
        As[buf][ac8 + 2][arow] = pa0.z; As[buf][ac8 + 3][arow] = pa0.w;
        As[buf][ac8 + 4][arow] = pa1.x; As[buf][ac8 + 5][arow] = pa1.y;
        As[buf][ac8 + 6][arow] = pa1.z; As[buf][ac8 + 7][arow] = pa1.w;
        *(float4*)&Bs[buf][brow][bcol]     = pb0;
        *(float4*)&Bs[buf][brow][bcol + 4] = pb1;
        __syncthreads();
    }

    // attention vectors for my 8 columns
    float as8[8], ad8[8];
    if (ATTH) {
        int hoff = (ATTH == 2) ? blockIdx.x * 128 : 0;
#pragma unroll
        for (int j = 0; j < 8; j++) {
            as8[j] = a_s[hoff + tx * 8 + j];
            ad8[j] = a_d[hoff + tx * 8 + j];
        }
    }

#pragma unroll
    for (int i = 0; i < 8; i++) {
        float c[8];
#pragma unroll
        for (int jp = 0; jp < 4; jp++) {
            float2 v = unpack2(acc[i][jp]);
            c[2 * jp] = v.x; c[2 * jp + 1] = v.y;
        }
        if (ATTH) {
            float ss = 0.f, sd = 0.f;
#pragma unroll
            for (int j = 0; j < 8; j++) { ss += c[j] * as8[j]; sd += c[j] * ad8[j]; }
#pragma unroll
            for (int off = 8; off; off >>= 1) {
                ss += __shfl_xor_sync(0xffffffffu, ss, off);
                sd += __shfl_xor_sync(0xffffffffu, sd, off);
            }
            if (tx == 0) {
                int r = row0 + ty * 8 + i;
                int head = (ATTH == 2) ? blockIdx.x : 0;
                atts[r * heads + head] = ss;
                attd[r * heads + head] = sd;
            }
        }
        size_t r = row0 + ty * 8 + i;
#pragma unroll
        for (int h = 0; h < 2; h++) {
            int col = col0 + tx * 8 + h * 4;
            float4 v;
            v.x = c[h * 4 + 0]; v.y = c[h * 4 + 1];
            v.z = c[h * 4 + 2]; v.w = c[h * 4 + 3];
            if (bias) {
                float4 bv = *(const float4*)&bias[col];
                v.x += bv.x; v.y += bv.y; v.z += bv.z; v.w += bv.w;
            }
            if (ACT == 1) {
                v.x = fmaxf(v.x, 0.f); v.y = fmaxf(v.y, 0.f);
                v.z = fmaxf(v.z, 0.f); v.w = fmaxf(v.w, 0.f);
            }
            *(float4*)&C[r * Nn + col] = v;
        }
    }
}

__global__ void __launch_bounds__(256) k_gemm1(const float* x, const float* W1,
                                               const float* as1, const float* ad1) {
    sgemm_core<0, 2>(x, W1, nullptr, g_h1, NN, 512, 128, as1, ad1, g_att1s, g_att1d, 4);
}
__global__ void __launch_bounds__(256) k_gemm2(const float* W2,
                                               const float* as2, const float* ad2) {
    sgemm_core<0, 1>(g_e1, W2, nullptr, g_h2, NN, 128, 512, as2, ad2, g_att2s, g_att2d, 1);
}
__global__ void __launch_bounds__(256) k_gemm3(const float* Wo1, const float* bo1) {
    sgemm_core<1, 0>(g_t, Wo1, bo1, g_u, NN, 128, 128, nullptr, nullptr, nullptr, nullptr, 1);
}
__global__ void __launch_bounds__(256) k_gemm4(const float* Wo2, const float* bo2, float* xo) {
    sgemm_core<0, 0>(g_u, Wo2, bo2, xo, NN, 128, 128, nullptr, nullptr, nullptr, nullptr, 1);
}
__global__ void __launch_bounds__(256) k_gemmP(const float* xo, const float* We1, const float* be1) {
    sgemm_core<0, 0>(xo, We1, be1, g_P, NN, 128, 128, nullptr, nullptr, nullptr, nullptr, 1);
}
__global__ void __launch_bounds__(256) k_gemmQ(const float* xo, const float* We1) {
    sgemm_core<0, 0>(xo, We1 + 128 * 128, nullptr, g_Q, NN, 128, 128, nullptr, nullptr, nullptr, nullptr, 1);
}

// ---------------- layer-1 aggregation: block per dst node, 128 threads ----------------
__global__ void __launch_bounds__(128) k_agg1(const float* __restrict__ b1) {
    const int n = blockIdx.x, tid = threadIdx.x;
    const int lane = tid & 31;
    const int h = tid >> 5;                 // head for my 4 channels (tid*4 .. tid*4+3)
    const int beg = g_off[n], end = g_off[n + 1];

    __shared__ float sden[4];
    __shared__ float s_ex[128 * 4];
    __shared__ int   s_s[128];
    if (tid < 4) sden[tid] = 0.f;
    __syncthreads();

    const float4 ad = *(const float4*)&g_att1d[n * 4];

    // pass 1: softmax denominators (no max subtraction needed: |alpha| small)
    float d0 = 0.f, d1 = 0.f, d2 = 0.f, d3 = 0.f;
    for (int i = beg + tid; i < end; i += 128) {
        int s = g_csrc[i];
        float4 as = *(const float4*)&g_att1s[s * 4];
        d0 += expf(lrelu02(as.x + ad.x));
        d1 += expf(lrelu02(as.y + ad.y));
        d2 += expf(lrelu02(as.z + ad.z));
        d3 += expf(lrelu02(as.w + ad.w));
    }
#pragma unroll
    for (int off = 16; off; off >>= 1) {
        d0 += __shfl_xor_sync(0xffffffffu, d0, off);
        d1 += __shfl_xor_sync(0xffffffffu, d1, off);
        d2 += __shfl_xor_sync(0xffffffffu, d2, off);
        d3 += __shfl_xor_sync(0xffffffffu, d3, off);
    }
    if (lane == 0) {
        atomicAdd(&sden[0], d0);
        atomicAdd(&sden[1], d1);
        atomicAdd(&sden[2], d2);
        atomicAdd(&sden[3], d3);
    }
    __syncthreads();
    const float invden = 1.f / sden[h];

    // pass 2: weighted sum of h1[src] rows
    float4 acc = make_float4(0.f, 0.f, 0.f, 0.f);
    for (int c0 = beg; c0 < end; c0 += 128) {
        int m = min(128, end - c0);
        if (tid < m) {
            int s = g_csrc[c0 + tid];
            s_s[tid] = s;
            float4 as = *(const float4*)&g_att1s[s * 4];
            s_ex[tid * 4 + 0] = expf(lrelu02(as.x + ad.x));
            s_ex[tid * 4 + 1] = expf(lrelu02(as.y + ad.y));
            s_ex[tid * 4 + 2] = expf(lrelu02(as.z + ad.z));
            s_ex[tid * 4 + 3] = expf(lrelu02(as.w + ad.w));
        }
        __syncthreads();
        for (int j = 0; j < m; j++) {
            float w = s_ex[j * 4 + h] * invden;
            float4 hv = *(const float4*)&g_h1[(size_t)s_s[j] * 512 + tid * 4];
            acc.x += hv.x * w; acc.y += hv.y * w;
            acc.z += hv.z * w; acc.w += hv.w * w;
        }
        __syncthreads();
    }
    float4 bv = *(const float4*)&b1[tid * 4];
    float4 o;
    o.x = eluf(acc.x + bv.x); o.y = eluf(acc.y + bv.y);
    o.z = eluf(acc.z + bv.z); o.w = eluf(acc.w + bv.w);
    *(float4*)&g_e1[(size_t)n * 512 + tid * 4] = o;
}

// ---------------- layer-2 aggregation (1 head, 128 channels) ----------------
__global__ void __launch_bounds__(128) k_agg2(const float* __restrict__ b2) {
    const int n = blockIdx.x, tid = threadIdx.x;
    const int lane = tid & 31;
    const int beg = g_off[n], end = g_off[n + 1];

    __shared__ float sden;
    __shared__ float s_ex[128];
    __shared__ int   s_s[128];
    if (tid == 0) sden = 0.f;
    __syncthreads();

    const float adn = g_att2d[n];

    float dsum = 0.f;
    for (int i = beg + tid; i < end; i += 128)
        dsum += expf(lrelu02(g_att2s[g_csrc[i]] + adn));
#pragma unroll
    for (int off = 16; off; off >>= 1) dsum += __shfl_xor_sync(0xffffffffu, dsum, off);
    if (lane == 0) atomicAdd(&sden, dsum);
    __syncthreads();
    const float invden = 1.f / sden;

    float acc = 0.f;
    for (int c0 = beg; c0 < end; c0 += 128) {
        int m = min(128, end - c0);
        if (tid < m) {
            int s = g_csrc[c0 + tid];
            s_s[tid] = s;
            s_ex[tid] = expf(lrelu02(g_att2s[s] + adn));
        }
        __syncthreads();
        for (int j = 0; j < m; j++) {
            float w = s_ex[j] * invden;
            acc += g_h2[(size_t)s_s[j] * 128 + tid] * w;
        }
        __syncthreads();
    }
    g_t[(size_t)n * 128 + tid] = eluf(acc + b2[tid]);
}

// ---------------- fused edge MLP: hidden = relu(P[s]+Q[d]+ea@We1_ea); out = hidden@We2+be2 ----------------
__global__ void __launch_bounds__(256) k_edge_final(const void* __restrict__ ei,
                                                    const float* __restrict__ eattr,
                                                    const float* __restrict__ We1,
                                                    const float* __restrict__ We2,
                                                    const float* __restrict__ be2,
                                                    float* __restrict__ out) {
    __shared__ float sW1[16 * 128];     // We1 rows 256..271
    __shared__ float sW2[128 * 16];
    __shared__ float sHid[8][128];
    const int tid = threadIdx.x;
    for (int i = tid; i < 2048; i += 256) {
        sW1[i] = We1[256 * 128 + i];
        sW2[i] = We2[i];
    }
    const int is64 = g_is64;
    __syncthreads();

    const int warp = tid >> 5, lane = tid & 31;
    const long e = (long)blockIdx.x * 8 + warp;
    if (e < EE) {
        int s = idx_at(ei, e, is64);
        int d = idx_at(ei, (long)EE + e, is64);
        float4 p = *(const float4*)&g_P[(size_t)s * 128 + lane * 4];
        float4 q = *(const float4*)&g_Q[(size_t)d * 128 + lane * 4];
        float4 hv;
        hv.x = p.x + q.x; hv.y = p.y + q.y; hv.z = p.z + q.z; hv.w = p.w + q.w;
        float eav = (lane < 16) ? eattr[e * 16 + lane] : 0.f;
#pragma unroll
        for (int k = 0; k < 16; k++) {
            float ek = __shfl_sync(0xffffffffu, eav, k);
            float4 wv = *(const float4*)&sW1[k * 128 + lane * 4];
            hv.x += ek * wv.x; hv.y += ek * wv.y;
            hv.z += ek * wv.z; hv.w += ek * wv.w;
        }
        hv.x = fmaxf(hv.x, 0.f); hv.y = fmaxf(hv.y, 0.f);
        hv.z = fmaxf(hv.z, 0.f); hv.w = fmaxf(hv.w, 0.f);
        *(float4*)&sHid[warp][lane * 4] = hv;
    }
    __syncwarp();
    if (e < EE) {
        const int o = lane & 15, half = lane >> 4;
        float acc = 0.f;
#pragma unroll
        for (int c = 0; c < 64; c++) {
            int cc = half * 64 + c;
            acc += sHid[warp][cc] * sW2[cc * 16 + o];
        }
        acc += __shfl_xor_sync(0xffffffffu, acc, 16);
        if (lane < 16) out[e * 16 + lane] = acc + be2[lane];
    }
}

// ---------------- launcher ----------------
extern "C" void kernel_launch(void* const* d_in, const int* in_sizes, int n_in,
                              void* d_out, int out_size) {
    const float* x    = (const float*)d_in[0];
    const void*  ei   = d_in[1];
    const float* eatt = (const float*)d_in[2];
    const float* W1   = (const float*)d_in[3];
    const float* as1  = (const float*)d_in[4];
    const float* ad1  = (const float*)d_in[5];
    const float* b1   = (const float*)d_in[6];
    const float* W2   = (const float*)d_in[7];
    const float* as2  = (const float*)d_in[8];
    const float* ad2  = (const float*)d_in[9];
    const float* b2   = (const float*)d_in[10];
    const float* Wo1  = (const float*)d_in[11];
    const float* bo1  = (const float*)d_in[12];
    const float* Wo2  = (const float*)d_in[13];
    const float* bo2  = (const float*)d_in[14];
    const float* We1  = (const float*)d_in[15];
    const float* be1  = (const float*)d_in[16];
    const float* We2  = (const float*)d_in[17];
    const float* be2  = (const float*)d_in[18];

    float* out  = (float*)d_out;
    float* xo   = out;                          // [NN,128]
    float* eout = out + (size_t)NN * 128;       // [EE,16]

    // CSR build (by dst, self-loops appended)
    k_detect<<<1, 256>>>((const int*)ei);
    k_zero_deg<<<(NN + 255) / 256, 256>>>();
    k_hist<<<(ET + 255) / 256, 256>>>(ei);
    k_scan1<<<125, 256>>>();
    k_scan2<<<1, 128>>>();
    k_scan3<<<125, 256>>>();
    k_scatter<<<(ET + 255) / 256, 256>>>(ei);

    // layer 1 (attention dots fused into GEMM epilogue)
    k_gemm1<<<dim3(4, 250), 256>>>(x, W1, as1, ad1);
    k_agg1<<<NN, 128>>>(b1);

    // layer 2
    k_gemm2<<<dim3(1, 250), 256>>>(W2, as2, ad2);
    k_agg2<<<NN, 128>>>(b2);

    // output MLP -> xo
    k_gemm3<<<dim3(1, 250), 256>>>(Wo1, bo1);
    k_gemm4<<<dim3(1, 250), 256>>>(Wo2, bo2, xo);

    // edge MLP decomposition: P = xo@We1[0:128]+be1, Q = xo@We1[128:256]
    k_gemmP<<<dim3(1, 250), 256>>>(xo, We1, be1);
    k_gemmQ<<<dim3(1, 250), 256>>>(xo, We1);
    k_edge_final<<<EE / 8, 256>>>(ei, eatt, We1, We2, be2, eout);
}

// round 4
// speedup vs baseline: 1.2327x; 1.1215x over previous
#include <cuda_runtime.h>
#include <cuda_bf16.h>
#include <cstdint>

#define NN 32000
#define EE 512000
#define ET (EE + NN)
#define DD 128
#define HH 4
#define EAD 16

typedef __nv_bfloat16 bf16;

// ================= scratch =================
__device__ int   g_is64;
__device__ int   g_deg[NN];
__device__ int   g_off[NN + 1];
__device__ int   g_cur[NN];
__device__ int   g_csrc[ET];
__device__ int   g_bsum[128];
__device__ int   g_boff[128];

__device__ float g_h1[(size_t)NN * 512];
__device__ float g_h2[(size_t)NN * 128];
__device__ float g_att1s[NN * 4];
__device__ float g_att1d[NN * 4];
__device__ float g_att2s[NN];
__device__ float g_att2d[NN];
__device__ float g_P[(size_t)NN * 128];
__device__ float g_Q[(size_t)NN * 128];

// bf16 split activations: [hi | hi | lo], pitch = 3*K
__device__ bf16  g_xp [(size_t)NN * 384];
__device__ bf16  g_e1p[(size_t)NN * 1536];
__device__ bf16  g_tp [(size_t)NN * 384];
__device__ bf16  g_up [(size_t)NN * 384];
__device__ bf16  g_xop[(size_t)NN * 384];
// bf16 split transposed weights: [N, 3K] = [hi | lo | hi]
__device__ bf16  g_W1t [512 * 384];
__device__ bf16  g_W2t [128 * 1536];
__device__ bf16  g_Wo1t[128 * 384];
__device__ bf16  g_Wo2t[128 * 384];
__device__ bf16  g_WePt[128 * 384];
__device__ bf16  g_WeQt[128 * 384];

// ================= helpers =================
__device__ __forceinline__ float lrelu02(float a) { return a > 0.f ? a : 0.2f * a; }
__device__ __forceinline__ float eluf(float v)    { return v > 0.f ? v : expm1f(v); }
__device__ __forceinline__ int idx_at(const void* ei, long pos, int is64) {
    if (is64) return (int)((const long long*)ei)[pos];
    return ((const int*)ei)[pos];
}
__device__ __forceinline__ void split_bf16(float v, bf16& h, bf16& l) {
    h = __float2bfloat16(v);
    l = __float2bfloat16(v - __bfloat162float(h));
}
__device__ __forceinline__ uint32_t smem_u32(const void* p) {
    uint32_t a;
    asm("{ .reg .u64 t; cvta.to.shared.u64 t, %1; cvt.u32.u64 %0, t; }" : "=r"(a) : "l"(p));
    return a;
}
__device__ __forceinline__ void cp_async16(uint32_t saddr, const void* g) {
    asm volatile("cp.async.cg.shared.global [%0], [%1], 16;" :: "r"(saddr), "l"(g));
}
__device__ __forceinline__ void mma_bf16(float* c, const uint32_t* a, const uint32_t* b) {
    asm volatile(
        "mma.sync.aligned.m16n8k16.row.col.f32.bf16.bf16.f32 "
        "{%0,%1,%2,%3}, {%4,%5,%6,%7}, {%8,%9}, {%0,%1,%2,%3};"
        : "+f"(c[0]), "+f"(c[1]), "+f"(c[2]), "+f"(c[3])
        : "r"(a[0]), "r"(a[1]), "r"(a[2]), "r"(a[3]), "r"(b[0]), "r"(b[1]));
}

// ================= CSR build =================
__global__ void k_detect(const int* w) {
    __shared__ int s_any;
    if (threadIdx.x == 0) s_any = 0;
    __syncthreads();
    int any = 0;
    for (int i = threadIdx.x; i < 1024; i += blockDim.x) any |= w[2 * i + 1];
    if (any) atomicOr(&s_any, 1);
    __syncthreads();
    if (threadIdx.x == 0) g_is64 = (s_any == 0) ? 1 : 0;
}
__global__ void k_zero_deg() {
    int i = blockIdx.x * blockDim.x + threadIdx.x;
    if (i < NN) g_deg[i] = 0;
}
__global__ void k_hist(const void* ei) {
    int is64 = g_is64;
    long e = (long)blockIdx.x * blockDim.x + threadIdx.x;
    if (e >= ET) return;
    int d = (e < EE) ? idx_at(ei, (long)EE + e, is64) : (int)(e - EE);
    atomicAdd(&g_deg[d], 1);
}
__global__ void k_scan1() {
    __shared__ int s[256];
    const int tid = threadIdx.x;
    const int idx = blockIdx.x * 256 + tid;
    int v = g_deg[idx];
    s[tid] = v;
    __syncthreads();
#pragma unroll
    for (int off = 1; off < 256; off <<= 1) {
        int t = (tid >= off) ? s[tid - off] : 0;
        __syncthreads();
        s[tid] += t;
        __syncthreads();
    }
    g_off[idx] = s[tid] - v;
    if (tid == 255) g_bsum[blockIdx.x] = s[255];
}
__global__ void k_scan2() {
    __shared__ int s[128];
    const int tid = threadIdx.x;
    int v = (tid < 125) ? g_bsum[tid] : 0;
    s[tid] = v;
    __syncthreads();
#pragma unroll
    for (int off = 1; off < 128; off <<= 1) {
        int t = (tid >= off) ? s[tid - off] : 0;
        __syncthreads();
        s[tid] += t;
        __syncthreads();
    }
    if (tid < 125) g_boff[tid] = s[tid] - v;
    if (tid == 127) g_off[NN] = s[127];
}
__global__ void k_scan3() {
    const int idx = blockIdx.x * 256 + threadIdx.x;
    int o = g_off[idx] + g_boff[blockIdx.x];
    g_off[idx] = o;
    g_cur[idx] = o;
}
__global__ void k_scatter(const void* ei) {
    int is64 = g_is64;
    long e = (long)blockIdx.x * blockDim.x + threadIdx.x;
    if (e >= ET) return;
    int s, d;
    if (e < EE) {
        s = idx_at(ei, e, is64);
        d = idx_at(ei, (long)EE + e, is64);
    } else {
        s = d = (int)(e - EE);
    }
    int pos = atomicAdd(&g_cur[d], 1);
    g_csrc[pos] = s;
}

// ================= conversions =================
__global__ void k_convA(const float* __restrict__ src, bf16* __restrict__ dst, int K, long total) {
    long i = (long)blockIdx.x * blockDim.x + threadIdx.x;
    if (i >= total) return;
    long m = i / K;
    int  k = (int)(i - m * K);
    bf16 h, l;
    split_bf16(src[i], h, l);
    bf16* row = dst + m * 3 * K;
    row[k] = h; row[K + k] = h; row[2 * K + k] = l;
}
__global__ void k_convW(const float* __restrict__ W, bf16* __restrict__ Wt, int K, int N) {
    long i = (long)blockIdx.x * blockDim.x + threadIdx.x;
    if (i >= (long)K * N) return;
    int n = (int)(i / K);
    int k = (int)(i - (long)n * K);
    bf16 h, l;
    split_bf16(W[(size_t)k * N + n], h, l);
    bf16* row = Wt + (size_t)n * 3 * K;
    row[k] = h; row[K + k] = l; row[2 * K + k] = h;
}

// ================= mma.sync split-bf16 GEMM =================
// C[M, Nn] = act( A'[M, KA] . B'[Nn, KA]^T + bias ), tile 128x128, BK=32,
// 256 threads = 8 warps (4m x 2n), warp tile 32x64.
// ACT: 0 none, 1 relu.  ATT: 0 none, 1 head0, 2 head=blockIdx.x
template <int ACT, int ATT>
__global__ void __launch_bounds__(256) k_mgemm(
    const bf16* __restrict__ Ap, const bf16* __restrict__ Bp,
    int KA, int Nn,
    const float* __restrict__ bias,
    float* __restrict__ Cf, bf16* __restrict__ Cb3,
    const float* __restrict__ a_s, const float* __restrict__ a_d,
    float* __restrict__ atts, float* __restrict__ attd, int heads)
{
    __shared__ bf16 As[2][128][40];
    __shared__ bf16 Bs[2][128][40];
    __shared__ float s_as[128], s_ad[128];

    const int tid = threadIdx.x;
    const int wid = tid >> 5, lane = tid & 31;
    const int g = lane >> 2, tig = lane & 3;
    const int warp_m = wid & 3, warp_n = wid >> 2;
    const int row0 = blockIdx.y * 128, col0 = blockIdx.x * 128;

    const int lr = tid >> 2, lc = (tid & 3) * 8;
    const bf16* Ag = Ap + (size_t)(row0 + lr) * KA + lc;
    const bf16* Bg = Bp + (size_t)(col0 + lr) * KA + lc;
    const uint32_t sA = smem_u32(&As[0][0][0]);
    const uint32_t sB = smem_u32(&Bs[0][0][0]);
    const uint32_t soffL = (uint32_t)lr * 80u + (uint32_t)lc * 2u;
    const uint32_t soffH = soffL + 64u * 80u;
    const size_t   gstep = (size_t)64 * KA;

    float c[2][8][4];
#pragma unroll
    for (int i = 0; i < 2; i++)
#pragma unroll
        for (int j = 0; j < 8; j++)
#pragma unroll
            for (int q = 0; q < 4; q++) c[i][j][q] = 0.f;

    cp_async16(sA + soffL, Ag);
    cp_async16(sA + soffH, Ag + gstep);
    cp_async16(sB + soffL, Bg);
    cp_async16(sB + soffH, Bg + gstep);
    asm volatile("cp.async.commit_group;" ::: "memory");

    const int NT = KA >> 5;
    for (int kt = 0; kt < NT; kt++) {
        const int buf = kt & 1;
        if (kt + 1 < NT) {
            const int koff = (kt + 1) * 32;
            const uint32_t bofs = ((kt + 1) & 1) ? 10240u : 0u;
            cp_async16(sA + bofs + soffL, Ag + koff);
            cp_async16(sA + bofs + soffH, Ag + gstep + koff);
            cp_async16(sB + bofs + soffL, Bg + koff);
            cp_async16(sB + bofs + soffH, Bg + gstep + koff);
            asm volatile("cp.async.commit_group;" ::: "memory");
            asm volatile("cp.async.wait_group 1;" ::: "memory");
        } else {
            asm volatile("cp.async.wait_group 0;" ::: "memory");
        }
        __syncthreads();

#pragma unroll
        for (int kk = 0; kk < 32; kk += 16) {
            uint32_t af[2][4], bf[8][2];
#pragma unroll
            for (int mi = 0; mi < 2; mi++) {
                const int r = warp_m * 32 + mi * 16 + g;
                af[mi][0] = *(const uint32_t*)&As[buf][r][kk + 2 * tig];
                af[mi][1] = *(const uint32_t*)&As[buf][r + 8][kk + 2 * tig];
                af[mi][2] = *(const uint32_t*)&As[buf][r][kk + 2 * tig + 8];
                af[mi][3] = *(const uint32_t*)&As[buf][r + 8][kk + 2 * tig + 8];
            }
#pragma unroll
            for (int ni = 0; ni < 8; ni++) {
                const int n = warp_n * 64 + ni * 8 + g;
                bf[ni][0] = *(const uint32_t*)&Bs[buf][n][kk + 2 * tig];
                bf[ni][1] = *(const uint32_t*)&Bs[buf][n][kk + 2 * tig + 8];
            }
#pragma unroll
            for (int mi = 0; mi < 2; mi++)
#pragma unroll
                for (int ni = 0; ni < 8; ni++)
                    mma_bf16(c[mi][ni], af[mi], bf[ni]);
        }
        __syncthreads();
    }

    if (ATT) {
        if (tid < 128) { s_as[tid] = 0.f; s_ad[tid] = 0.f; }
        __syncthreads();
    }

    float ssv[2][2] = {{0.f, 0.f}, {0.f, 0.f}};
    float sdv[2][2] = {{0.f, 0.f}, {0.f, 0.f}};

#pragma unroll
    for (int ni = 0; ni < 8; ni++) {
        const int cA = col0 + warp_n * 64 + ni * 8 + tig * 2;
        float b0 = 0.f, b1 = 0.f;
        if (bias) { b0 = __ldg(&bias[cA]); b1 = __ldg(&bias[cA + 1]); }
        float asA = 0.f, asB = 0.f, adA = 0.f, adB = 0.f;
        if (ATT) {
            asA = __ldg(&a_s[cA]); asB = __ldg(&a_s[cA + 1]);
            adA = __ldg(&a_d[cA]); adB = __ldg(&a_d[cA + 1]);
        }
#pragma unroll
        for (int mi = 0; mi < 2; mi++) {
            const int r0g = row0 + warp_m * 32 + mi * 16 + g;
            const int r1g = r0g + 8;
            float v00 = c[mi][ni][0] + b0, v01 = c[mi][ni][1] + b1;
            float v10 = c[mi][ni][2] + b0, v11 = c[mi][ni][3] + b1;
            if (ACT == 1) {
                v00 = fmaxf(v00, 0.f); v01 = fmaxf(v01, 0.f);
                v10 = fmaxf(v10, 0.f); v11 = fmaxf(v11, 0.f);
            }
            if (ATT) {
                ssv[mi][0] += v00 * asA + v01 * asB;
                ssv[mi][1] += v10 * asA + v11 * asB;
                sdv[mi][0] += v00 * adA + v01 * adB;
                sdv[mi][1] += v10 * adA + v11 * adB;
            }
            if (Cf) {
                *(float2*)&Cf[(size_t)r0g * Nn + cA] = make_float2(v00, v01);
                *(float2*)&Cf[(size_t)r1g * Nn + cA] = make_float2(v10, v11);
            }
            if (Cb3) {
                bf16 h0, l0, h1, l1;
                __nv_bfloat162 hp, lp;
                size_t rb0 = (size_t)r0g * 3 * Nn;
                split_bf16(v00, h0, l0); split_bf16(v01, h1, l1);
                hp.x = h0; hp.y = h1; lp.x = l0; lp.y = l1;
                *(__nv_bfloat162*)&Cb3[rb0 + cA]          = hp;
                *(__nv_bfloat162*)&Cb3[rb0 + Nn + cA]     = hp;
                *(__nv_bfloat162*)&Cb3[rb0 + 2 * Nn + cA] = lp;
                size_t rb1 = (size_t)r1g * 3 * Nn;
                split_bf16(v10, h0, l0); split_bf16(v11, h1, l1);
                hp.x = h0; hp.y = h1; lp.x = l0; lp.y = l1;
                *(__nv_bfloat162*)&Cb3[rb1 + cA]          = hp;
                *(__nv_bfloat162*)&Cb3[rb1 + Nn + cA]     = hp;
                *(__nv_bfloat162*)&Cb3[rb1 + 2 * Nn + cA] = lp;
            }
        }
    }

    if (ATT) {
#pragma unroll
        for (int mi = 0; mi < 2; mi++) {
            const int rl0 = warp_m * 32 + mi * 16 + g;
            atomicAdd(&s_as[rl0], ssv[mi][0]);
            atomicAdd(&s_as[rl0 + 8], ssv[mi][1]);
            atomicAdd(&s_ad[rl0], sdv[mi][0]);
            atomicAdd(&s_ad[rl0 + 8], sdv[mi][1]);
        }
        __syncthreads();
        if (tid < 128) {
            const int head = (ATT == 2) ? (int)blockIdx.x : 0;
            const int row = row0 + tid;
            atts[row * heads + head] = s_as[tid];
            attd[row * heads + head] = s_ad[tid];
        }
    }
}

// ================= layer-1 aggregation =================
__global__ void __launch_bounds__(128) k_agg1(const float* __restrict__ b1) {
    const int n = blockIdx.x, tid = threadIdx.x;
    const int lane = tid & 31;
    const int h = tid >> 5;
    const int beg = g_off[n], end = g_off[n + 1];

    __shared__ float sden[4];
    __shared__ float s_ex[128 * 4];
    __shared__ int   s_s[128];
    if (tid < 4) sden[tid] = 0.f;
    __syncthreads();

    const float4 ad = *(const float4*)&g_att1d[n * 4];

    float d0 = 0.f, d1 = 0.f, d2 = 0.f, d3 = 0.f;
    for (int i = beg + tid; i < end; i += 128) {
        int s = g_csrc[i];
        float4 as = *(const float4*)&g_att1s[s * 4];
        d0 += expf(lrelu02(as.x + ad.x));
        d1 += expf(lrelu02(as.y + ad.y));
        d2 += expf(lrelu02(as.z + ad.z));
        d3 += expf(lrelu02(as.w + ad.w));
    }
#pragma unroll
    for (int off = 16; off; off >>= 1) {
        d0 += __shfl_xor_sync(0xffffffffu, d0, off);
        d1 += __shfl_xor_sync(0xffffffffu, d1, off);
        d2 += __shfl_xor_sync(0xffffffffu, d2, off);
        d3 += __shfl_xor_sync(0xffffffffu, d3, off);
    }
    if (lane == 0) {
        atomicAdd(&sden[0], d0);
        atomicAdd(&sden[1], d1);
        atomicAdd(&sden[2], d2);
        atomicAdd(&sden[3], d3);
    }
    __syncthreads();
    const float invden = 1.f / sden[h];

    float4 acc = make_float4(0.f, 0.f, 0.f, 0.f);
    for (int c0 = beg; c0 < end; c0 += 128) {
        int mcnt = min(128, end - c0);
        if (tid < mcnt) {
            int s = g_csrc[c0 + tid];
            s_s[tid] = s;
            float4 as = *(const float4*)&g_att1s[s * 4];
            s_ex[tid * 4 + 0] = expf(lrelu02(as.x + ad.x));
            s_ex[tid * 4 + 1] = expf(lrelu02(as.y + ad.y));
            s_ex[tid * 4 + 2] = expf(lrelu02(as.z + ad.z));
            s_ex[tid * 4 + 3] = expf(lrelu02(as.w + ad.w));
        }
        __syncthreads();
        for (int j = 0; j < mcnt; j++) {
            float w = s_ex[j * 4 + h] * invden;
            float4 hv = *(const float4*)&g_h1[(size_t)s_s[j] * 512 + tid * 4];
            acc.x += hv.x * w; acc.y += hv.y * w;
            acc.z += hv.z * w; acc.w += hv.w * w;
        }
        __syncthreads();
    }
    float4 bv = *(const float4*)&b1[tid * 4];
    float o0 = eluf(acc.x + bv.x), o1 = eluf(acc.y + bv.y);
    float o2 = eluf(acc.z + bv.z), o3 = eluf(acc.w + bv.w);
    bf16 h0, l0, h1b, l1, h2b, l2, h3b, l3;
    split_bf16(o0, h0, l0); split_bf16(o1, h1b, l1);
    split_bf16(o2, h2b, l2); split_bf16(o3, h3b, l3);
    __nv_bfloat162 hA, hB, lA, lB;
    hA.x = h0; hA.y = h1b; hB.x = h2b; hB.y = h3b;
    lA.x = l0; lA.y = l1;  lB.x = l2;  lB.y = l3;
    const size_t rb = (size_t)n * 1536;
    const int cb = tid * 4;
    *(__nv_bfloat162*)&g_e1p[rb + cb]            = hA;
    *(__nv_bfloat162*)&g_e1p[rb + cb + 2]        = hB;
    *(__nv_bfloat162*)&g_e1p[rb + 512 + cb]      = hA;
    *(__nv_bfloat162*)&g_e1p[rb + 512 + cb + 2]  = hB;
    *(__nv_bfloat162*)&g_e1p[rb + 1024 + cb]     = lA;
    *(__nv_bfloat162*)&g_e1p[rb + 1024 + cb + 2] = lB;
}

// ================= layer-2 aggregation =================
__global__ void __launch_bounds__(128) k_agg2(const float* __restrict__ b2) {
    const int n = blockIdx.x, tid = threadIdx.x;
    const int lane = tid & 31;
    const int beg = g_off[n], end = g_off[n + 1];

    __shared__ float sden;
    __shared__ float s_ex[128];
    __shared__ int   s_s[128];
    if (tid == 0) sden = 0.f;
    __syncthreads();

    const float adn = g_att2d[n];

    float dsum = 0.f;
    for (int i = beg + tid; i < end; i += 128)
        dsum += expf(lrelu02(g_att2s[g_csrc[i]] + adn));
#pragma unroll
    for (int off = 16; off; off >>= 1) dsum += __shfl_xor_sync(0xffffffffu, dsum, off);
    if (lane == 0) atomicAdd(&sden, dsum);
    __syncthreads();
    const float invden = 1.f / sden;

    float acc = 0.f;
    for (int c0 = beg; c0 < end; c0 += 128) {
        int mcnt = min(128, end - c0);
        if (tid < mcnt) {
            int s = g_csrc[c0 + tid];
            s_s[tid] = s;
            s_ex[tid] = expf(lrelu02(g_att2s[s] + adn));
        }
        __syncthreads();
        for (int j = 0; j < mcnt; j++) {
            float w = s_ex[j] * invden;
            acc += g_h2[(size_t)s_s[j] * 128 + tid] * w;
        }
        __syncthreads();
    }
    float o = eluf(acc + b2[tid]);
    bf16 h, l;
    split_bf16(o, h, l);
    g_tp[(size_t)n * 384 + tid]       = h;
    g_tp[(size_t)n * 384 + 128 + tid] = h;
    g_tp[(size_t)n * 384 + 256 + tid] = l;
}

// ================= fused edge MLP =================
__global__ void __launch_bounds__(256) k_edge_final(const void* __restrict__ ei,
                                                    const float* __restrict__ eattr,
                                                    const float* __restrict__ We1,
                                                    const float* __restrict__ We2,
                                                    const float* __restrict__ be2,
                                                    float* __restrict__ out) {
    __shared__ float sW1[16 * 128];
    __shared__ float sW2[128 * 16];
    __shared__ float sHid[8][128];
    const int tid = threadIdx.x;
    for (int i = tid; i < 2048; i += 256) {
        sW1[i] = We1[256 * 128 + i];
        sW2[i] = We2[i];
    }
    const int is64 = g_is64;
    __syncthreads();

    const int warp = tid >> 5, lane = tid & 31;
    const long e = (long)blockIdx.x * 8 + warp;
    if (e < EE) {
        int s = idx_at(ei, e, is64);
        int d = idx_at(ei, (long)EE + e, is64);
        float4 p = *(const float4*)&g_P[(size_t)s * 128 + lane * 4];
        float4 q = *(const float4*)&g_Q[(size_t)d * 128 + lane * 4];
        float4 hv;
        hv.x = p.x + q.x; hv.y = p.y + q.y; hv.z = p.z + q.z; hv.w = p.w + q.w;
        float eav = (lane < 16) ? eattr[e * 16 + lane] : 0.f;
#pragma unroll
        for (int k = 0; k < 16; k++) {
            float ek = __shfl_sync(0xffffffffu, eav, k);
            float4 wv = *(const float4*)&sW1[k * 128 + lane * 4];
            hv.x += ek * wv.x; hv.y += ek * wv.y;
            hv.z += ek * wv.z; hv.w += ek * wv.w;
        }
        hv.x = fmaxf(hv.x, 0.f); hv.y = fmaxf(hv.y, 0.f);
        hv.z = fmaxf(hv.z, 0.f); hv.w = fmaxf(hv.w, 0.f);
        *(float4*)&sHid[warp][lane * 4] = hv;
    }
    __syncwarp();
    if (e < EE) {
        const int o = lane & 15, half = lane >> 4;
        float acc = 0.f;
#pragma unroll
        for (int c = 0; c < 64; c++) {
            int cc = half * 64 + c;
            acc += sHid[warp][cc] * sW2[cc * 16 + o];
        }
        acc += __shfl_xor_sync(0xffffffffu, acc, 16);
        if (lane < 16) out[e * 16 + lane] = acc + be2[lane];
    }
}

// ================= launcher =================
extern "C" void kernel_launch(void* const* d_in, const int* in_sizes, int n_in,
                              void* d_out, int out_size) {
    const float* x    = (const float*)d_in[0];
    const void*  ei   = d_in[1];
    const float* eatt = (const float*)d_in[2];
    const float* W1   = (const float*)d_in[3];
    const float* as1  = (const float*)d_in[4];
    const float* ad1  = (const float*)d_in[5];
    const float* b1   = (const float*)d_in[6];
    const float* W2   = (const float*)d_in[7];
    const float* as2  = (const float*)d_in[8];
    const float* ad2  = (const float*)d_in[9];
    const float* b2   = (const float*)d_in[10];
    const float* Wo1  = (const float*)d_in[11];
    const float* bo1  = (const float*)d_in[12];
    const float* Wo2  = (const float*)d_in[13];
    const float* bo2  = (const float*)d_in[14];
    const float* We1  = (const float*)d_in[15];
    const float* be1  = (const float*)d_in[16];
    const float* We2  = (const float*)d_in[17];
    const float* be2  = (const float*)d_in[18];

    float* out  = (float*)d_out;
    float* xo   = out;
    float* eout = out + (size_t)NN * 128;

    bf16 *xp, *e1p, *tp, *up, *xop, *W1t, *W2t, *Wo1t, *Wo2t, *WePt, *WeQt;
    float *h1, *h2, *P, *Q, *a1s, *a1d, *a2s, *a2d;
    cudaGetSymbolAddress((void**)&xp,  g_xp);
    cudaGetSymbolAddress((void**)&e1p, g_e1p);
    cudaGetSymbolAddress((void**)&tp,  g_tp);
    cudaGetSymbolAddress((void**)&up,  g_up);
    cudaGetSymbolAddress((void**)&xop, g_xop);
    cudaGetSymbolAddress((void**)&W1t, g_W1t);
    cudaGetSymbolAddress((void**)&W2t, g_W2t);
    cudaGetSymbolAddress((void**)&Wo1t, g_Wo1t);
    cudaGetSymbolAddress((void**)&Wo2t, g_Wo2t);
    cudaGetSymbolAddress((void**)&WePt, g_WePt);
    cudaGetSymbolAddress((void**)&WeQt, g_WeQt);
    cudaGetSymbolAddress((void**)&h1, g_h1);
    cudaGetSymbolAddress((void**)&h2, g_h2);
    cudaGetSymbolAddress((void**)&P,  g_P);
    cudaGetSymbolAddress((void**)&Q,  g_Q);
    cudaGetSymbolAddress((void**)&a1s, g_att1s);
    cudaGetSymbolAddress((void**)&a1d, g_att1d);
    cudaGetSymbolAddress((void**)&a2s, g_att2s);
    cudaGetSymbolAddress((void**)&a2d, g_att2d);

    // CSR build
    k_detect<<<1, 256>>>((const int*)ei);
    k_zero_deg<<<(NN + 255) / 256, 256>>>();
    k_hist<<<(ET + 255) / 256, 256>>>(ei);
    k_scan1<<<125, 256>>>();
    k_scan2<<<1, 128>>>();
    k_scan3<<<125, 256>>>();
    k_scatter<<<(ET + 255) / 256, 256>>>(ei);

    // conversions
    k_convA<<<(int)(((long)NN * 128 + 255) / 256), 256>>>(x, xp, 128, (long)NN * 128);
    k_convW<<<(128 * 512 + 255) / 256, 256>>>(W1, W1t, 128, 512);
    k_convW<<<(512 * 128 + 255) / 256, 256>>>(W2, W2t, 512, 128);
    k_convW<<<(128 * 128 + 255) / 256, 256>>>(Wo1, Wo1t, 128, 128);
    k_convW<<<(128 * 128 + 255) / 256, 256>>>(Wo2, Wo2t, 128, 128);
    k_convW<<<(128 * 128 + 255) / 256, 256>>>(We1, WePt, 128, 128);
    k_convW<<<(128 * 128 + 255) / 256, 256>>>(We1 + 128 * 128, WeQt, 128, 128);

    // layer 1 (att dots fused)
    k_mgemm<0, 2><<<dim3(4, 250), 256>>>(xp, W1t, 384, 512,
        nullptr, h1, nullptr, as1, ad1, a1s, a1d, 4);
    k_agg1<<<NN, 128>>>(b1);

    // layer 2
    k_mgemm<0, 1><<<dim3(1, 250), 256>>>(e1p, W2t, 1536, 128,
        nullptr, h2, nullptr, as2, ad2, a2s, a2d, 1);
    k_agg2<<<NN, 128>>>(b2);

    // output MLP
    k_mgemm<1, 0><<<dim3(1, 250), 256>>>(tp, Wo1t, 384, 128,
        bo1, nullptr, up, nullptr, nullptr, nullptr, nullptr, 1);
    k_mgemm<0, 0><<<dim3(1, 250), 256>>>(up, Wo2t, 384, 128,
        bo2, xo, xop, nullptr, nullptr, nullptr, nullptr, 1);

    // edge MLP decomposition
    k_mgemm<0, 0><<<dim3(1, 250), 256>>>(xop, WePt, 384, 128,
        be1, P, nullptr, nullptr, nullptr, nullptr, nullptr, 1);
    k_mgemm<0, 0><<<dim3(1, 250), 256>>>(xop, WeQt, 384, 128,
        nullptr, Q, nullptr, nullptr, nullptr, nullptr, nullptr, 1);
    k_edge_final<<<EE / 8, 256>>>(ei, eatt, We1, We2, be2, eout);
}

// round 5
// speedup vs baseline: 1.2977x; 1.0527x over previous
#include <cuda_runtime.h>
#include <cuda_bf16.h>
#include <cuda_fp16.h>
#include <cstdint>

#define NN 32000
#define EE 512000
#define ET (EE + NN)
#define DD 128
#define HH 4
#define EAD 16

typedef __nv_bfloat16 bf16;

// ================= scratch =================
__device__ int   g_is64;
__device__ int   g_deg[NN];
__device__ int   g_off[NN + 1];
__device__ int   g_cur[NN];
__device__ int   g_csrc[ET];
__device__ int   g_bsum[128];
__device__ int   g_boff[128];

__device__ __half g_h1h[(size_t)NN * 512];   // gemm1 out (fp16, gathered by agg1)
__device__ __half g_h2h[(size_t)NN * 128];   // gemm2 out (fp16, gathered by agg2)
__device__ float g_att1s[NN * 4];
__device__ float g_att1d[NN * 4];
__device__ float g_att2s[NN];
__device__ float g_att2d[NN];
__device__ float g_PQ[(size_t)NN * 256];     // [P | Q] per node
__device__ float g_bePQ[256];

// bf16 split activations: [hi | hi | lo], pitch = 3*K
__device__ bf16  g_xp [(size_t)NN * 384];
__device__ bf16  g_e1p[(size_t)NN * 1536];
__device__ bf16  g_tp [(size_t)NN * 384];
__device__ bf16  g_up [(size_t)NN * 384];
__device__ bf16  g_xop[(size_t)NN * 384];
// bf16 split transposed weights: [N, 3K] = [hi | lo | hi]
__device__ bf16  g_W1t  [512 * 384];
__device__ bf16  g_W2t  [128 * 1536];
__device__ bf16  g_Wo1t [128 * 384];
__device__ bf16  g_Wo2t [128 * 384];
__device__ bf16  g_WePQt[256 * 384];

// ================= helpers =================
__device__ __forceinline__ float lrelu02(float a) { return a > 0.f ? a : 0.2f * a; }
__device__ __forceinline__ float eluf(float v)    { return v > 0.f ? v : expm1f(v); }
__device__ __forceinline__ int idx_at(const void* ei, long pos, int is64) {
    if (is64) return (int)((const long long*)ei)[pos];
    return ((const int*)ei)[pos];
}
__device__ __forceinline__ void split_bf16(float v, bf16& h, bf16& l) {
    h = __float2bfloat16(v);
    l = __float2bfloat16(v - __bfloat162float(h));
}
__device__ __forceinline__ uint32_t smem_u32(const void* p) {
    uint32_t a;
    asm("{ .reg .u64 t; cvta.to.shared.u64 t, %1; cvt.u32.u64 %0, t; }" : "=r"(a) : "l"(p));
    return a;
}
__device__ __forceinline__ void cp_async16(uint32_t saddr, const void* g) {
    asm volatile("cp.async.cg.shared.global [%0], [%1], 16;" :: "r"(saddr), "l"(g));
}
__device__ __forceinline__ void mma_bf16(float* c, const uint32_t* a, const uint32_t* b) {
    asm volatile(
        "mma.sync.aligned.m16n8k16.row.col.f32.bf16.bf16.f32 "
        "{%0,%1,%2,%3}, {%4,%5,%6,%7}, {%8,%9}, {%0,%1,%2,%3};"
        : "+f"(c[0]), "+f"(c[1]), "+f"(c[2]), "+f"(c[3])
        : "r"(a[0]), "r"(a[1]), "r"(a[2]), "r"(a[3]), "r"(b[0]), "r"(b[1]));
}
__device__ __forceinline__ void ldm_x4(uint32_t* r, uint32_t addr) {
    asm volatile("ldmatrix.sync.aligned.m8n8.x4.shared.b16 {%0,%1,%2,%3}, [%4];"
                 : "=r"(r[0]), "=r"(r[1]), "=r"(r[2]), "=r"(r[3]) : "r"(addr));
}

// ================= CSR build =================
__global__ void k_detect(const int* w) {
    __shared__ int s_any;
    if (threadIdx.x == 0) s_any = 0;
    __syncthreads();
    int any = 0;
    for (int i = threadIdx.x; i < 1024; i += blockDim.x) any |= w[2 * i + 1];
    if (any) atomicOr(&s_any, 1);
    __syncthreads();
    if (threadIdx.x == 0) g_is64 = (s_any == 0) ? 1 : 0;
}
__global__ void k_zero_deg() {
    int i = blockIdx.x * blockDim.x + threadIdx.x;
    if (i < NN) g_deg[i] = 0;
}
__global__ void k_hist(const void* ei) {
    int is64 = g_is64;
    long e = (long)blockIdx.x * blockDim.x + threadIdx.x;
    if (e >= ET) return;
    int d = (e < EE) ? idx_at(ei, (long)EE + e, is64) : (int)(e - EE);
    atomicAdd(&g_deg[d], 1);
}
__global__ void k_scan1() {
    __shared__ int s[256];
    const int tid = threadIdx.x;
    const int idx = blockIdx.x * 256 + tid;
    int v = g_deg[idx];
    s[tid] = v;
    __syncthreads();
#pragma unroll
    for (int off = 1; off < 256; off <<= 1) {
        int t = (tid >= off) ? s[tid - off] : 0;
        __syncthreads();
        s[tid] += t;
        __syncthreads();
    }
    g_off[idx] = s[tid] - v;
    if (tid == 255) g_bsum[blockIdx.x] = s[255];
}
__global__ void k_scan2() {
    __shared__ int s[128];
    const int tid = threadIdx.x;
    int v = (tid < 125) ? g_bsum[tid] : 0;
    s[tid] = v;
    __syncthreads();
#pragma unroll
    for (int off = 1; off < 128; off <<= 1) {
        int t = (tid >= off) ? s[tid - off] : 0;
        __syncthreads();
        s[tid] += t;
        __syncthreads();
    }
    if (tid < 125) g_boff[tid] = s[tid] - v;
    if (tid == 127) g_off[NN] = s[127];
}
__global__ void k_scan3() {
    const int idx = blockIdx.x * 256 + threadIdx.x;
    int o = g_off[idx] + g_boff[blockIdx.x];
    g_off[idx] = o;
    g_cur[idx] = o;
}
__global__ void k_scatter(const void* ei) {
    int is64 = g_is64;
    long e = (long)blockIdx.x * blockDim.x + threadIdx.x;
    if (e >= ET) return;
    int s, d;
    if (e < EE) {
        s = idx_at(ei, e, is64);
        d = idx_at(ei, (long)EE + e, is64);
    } else {
        s = d = (int)(e - EE);
    }
    int pos = atomicAdd(&g_cur[d], 1);
    g_csrc[pos] = s;
}

// ================= conversions =================
__global__ void k_convA(const float* __restrict__ src, bf16* __restrict__ dst, int K, long total) {
    long i = (long)blockIdx.x * blockDim.x + threadIdx.x;
    if (i >= total) return;
    long m = i / K;
    int  k = (int)(i - m * K);
    bf16 h, l;
    split_bf16(src[i], h, l);
    bf16* row = dst + m * 3 * K;
    row[k] = h; row[K + k] = h; row[2 * K + k] = l;
}
__global__ void k_convW(const float* __restrict__ W, bf16* __restrict__ Wt, int K, int N) {
    long i = (long)blockIdx.x * blockDim.x + threadIdx.x;
    if (i >= (long)K * N) return;
    int n = (int)(i / K);
    int k = (int)(i - (long)n * K);
    bf16 h, l;
    split_bf16(W[(size_t)k * N + n], h, l);
    bf16* row = Wt + (size_t)n * 3 * K;
    row[k] = h; row[K + k] = l; row[2 * K + k] = h;
}
__global__ void k_mkbias(const float* be1) {
    int i = threadIdx.x;
    g_bePQ[i] = (i < 128) ? be1[i] : 0.f;
}

// ================= mma.sync split-bf16 GEMM (ldmatrix fragments) =================
// C[M, Nn] = act( A'[M, KA] . B'[Nn, KA]^T + bias ), tile 128x128, BK=32,
// 256 threads = 8 warps (4m x 2n), warp tile 32x64.
// ACT: 0 none, 1 relu.  ATT: 0 none, 1 head0, 2 head=blockIdx.x
template <int ACT, int ATT>
__global__ void __launch_bounds__(256) k_mgemm(
    const bf16* __restrict__ Ap, const bf16* __restrict__ Bp,
    int KA, int Nn,
    const float* __restrict__ bias,
    float* __restrict__ Cf, __half* __restrict__ Ch, bf16* __restrict__ Cb3,
    const float* __restrict__ a_s, const float* __restrict__ a_d,
    float* __restrict__ atts, float* __restrict__ attd, int heads)
{
    __shared__ bf16 As[2][128][40];
    __shared__ bf16 Bs[2][128][40];
    __shared__ float s_as[128], s_ad[128];

    const int tid = threadIdx.x;
    const int wid = tid >> 5, lane = tid & 31;
    const int g = lane >> 2, tig = lane & 3;
    const int warp_m = wid & 3, warp_n = wid >> 2;
    const int row0 = blockIdx.y * 128, col0 = blockIdx.x * 128;

    const int lr = tid >> 2, lc = (tid & 3) * 8;
    const bf16* Ag = Ap + (size_t)(row0 + lr) * KA + lc;
    const bf16* Bg = Bp + (size_t)(col0 + lr) * KA + lc;
    const uint32_t sA = smem_u32(&As[0][0][0]);
    const uint32_t sB = smem_u32(&Bs[0][0][0]);
    const uint32_t soffL = (uint32_t)lr * 80u + (uint32_t)lc * 2u;
    const uint32_t soffH = soffL + 64u * 80u;
    const size_t   gstep = (size_t)64 * KA;

    // ldmatrix per-lane address components
    const int arow_l = (((lane >> 3) & 1) << 3) + (lane & 7);  // row within 16
    const int acol_l = (lane >> 4) << 3;                       // k half
    const int brow_l = (lane & 7) + ((lane >> 4) << 3);        // row within 16 (2 n-blocks)
    const int bcol_l = ((lane >> 3) & 1) << 3;                 // k half

    float c[2][8][4];
#pragma unroll
    for (int i = 0; i < 2; i++)
#pragma unroll
        for (int j = 0; j < 8; j++)
#pragma unroll
            for (int q = 0; q < 4; q++) c[i][j][q] = 0.f;

    cp_async16(sA + soffL, Ag);
    cp_async16(sA + soffH, Ag + gstep);
    cp_async16(sB + soffL, Bg);
    cp_async16(sB + soffH, Bg + gstep);
    asm volatile("cp.async.commit_group;" ::: "memory");

    const int NT = KA >> 5;
    for (int kt = 0; kt < NT; kt++) {
        const int buf = kt & 1;
        if (kt + 1 < NT) {
            const int koff = (kt + 1) * 32;
            const uint32_t bofs = ((kt + 1) & 1) ? 10240u : 0u;
            cp_async16(sA + bofs + soffL, Ag + koff);
            cp_async16(sA + bofs + soffH, Ag + gstep + koff);
            cp_async16(sB + bofs + soffL, Bg + koff);
            cp_async16(sB + bofs + soffH, Bg + gstep + koff);
            asm volatile("cp.async.commit_group;" ::: "memory");
            asm volatile("cp.async.wait_group 1;" ::: "memory");
        } else {
            asm volatile("cp.async.wait_group 0;" ::: "memory");
        }
        __syncthreads();

        const uint32_t sAb = sA + (uint32_t)buf * 10240u;
        const uint32_t sBb = sB + (uint32_t)buf * 10240u;
#pragma unroll
        for (int kk = 0; kk < 32; kk += 16) {
            uint32_t af[2][4], bf[8][2];
#pragma unroll
            for (int mi = 0; mi < 2; mi++) {
                uint32_t addr = sAb + (uint32_t)(warp_m * 32 + mi * 16 + arow_l) * 80u
                                    + (uint32_t)(kk + acol_l) * 2u;
                ldm_x4(af[mi], addr);
            }
#pragma unroll
            for (int p = 0; p < 4; p++) {
                uint32_t r[4];
                uint32_t addr = sBb + (uint32_t)(warp_n * 64 + p * 16 + brow_l) * 80u
                                    + (uint32_t)(kk + bcol_l) * 2u;
                ldm_x4(r, addr);
                bf[2 * p][0] = r[0]; bf[2 * p][1] = r[1];
                bf[2 * p + 1][0] = r[2]; bf[2 * p + 1][1] = r[3];
            }
#pragma unroll
            for (int mi = 0; mi < 2; mi++)
#pragma unroll
                for (int ni = 0; ni < 8; ni++)
                    mma_bf16(c[mi][ni], af[mi], bf[ni]);
        }
        __syncthreads();
    }

    if (ATT) {
        if (tid < 128) { s_as[tid] = 0.f; s_ad[tid] = 0.f; }
        __syncthreads();
    }

    float ssv[2][2] = {{0.f, 0.f}, {0.f, 0.f}};
    float sdv[2][2] = {{0.f, 0.f}, {0.f, 0.f}};

#pragma unroll
    for (int ni = 0; ni < 8; ni++) {
        const int cA = col0 + warp_n * 64 + ni * 8 + tig * 2;
        float b0 = 0.f, b1 = 0.f;
        if (bias) { b0 = __ldg(&bias[cA]); b1 = __ldg(&bias[cA + 1]); }
        float asA = 0.f, asB = 0.f, adA = 0.f, adB = 0.f;
        if (ATT) {
            asA = __ldg(&a_s[cA]); asB = __ldg(&a_s[cA + 1]);
            adA = __ldg(&a_d[cA]); adB = __ldg(&a_d[cA + 1]);
        }
#pragma unroll
        for (int mi = 0; mi < 2; mi++) {
            const int r0g = row0 + warp_m * 32 + mi * 16 + g;
            const int r1g = r0g + 8;
            float v00 = c[mi][ni][0] + b0, v01 = c[mi][ni][1] + b1;
            float v10 = c[mi][ni][2] + b0, v11 = c[mi][ni][3] + b1;
            if (ACT == 1) {
                v00 = fmaxf(v00, 0.f); v01 = fmaxf(v01, 0.f);
                v10 = fmaxf(v10, 0.f); v11 = fmaxf(v11, 0.f);
            }
            if (ATT) {
                ssv[mi][0] += v00 * asA + v01 * asB;
                ssv[mi][1] += v10 * asA + v11 * asB;
                sdv[mi][0] += v00 * adA + v01 * adB;
                sdv[mi][1] += v10 * adA + v11 * adB;
            }
            if (Cf) {
                *(float2*)&Cf[(size_t)r0g * Nn + cA] = make_float2(v00, v01);
                *(float2*)&Cf[(size_t)r1g * Nn + cA] = make_float2(v10, v11);
            }
            if (Ch) {
                *(__half2*)&Ch[(size_t)r0g * Nn + cA] = __floats2half2_rn(v00, v01);
                *(__half2*)&Ch[(size_t)r1g * Nn + cA] = __floats2half2_rn(v10, v11);
            }
            if (Cb3) {
                bf16 h0, l0, h1, l1;
                __nv_bfloat162 hp, lp;
                size_t rb0 = (size_t)r0g * 3 * Nn;
                split_bf16(v00, h0, l0); split_bf16(v01, h1, l1);
                hp.x = h0; hp.y = h1; lp.x = l0; lp.y = l1;
                *(__nv_bfloat162*)&Cb3[rb0 + cA]          = hp;
                *(__nv_bfloat162*)&Cb3[rb0 + Nn + cA]     = hp;
                *(__nv_bfloat162*)&Cb3[rb0 + 2 * Nn + cA] = lp;
                size_t rb1 = (size_t)r1g * 3 * Nn;
                split_bf16(v10, h0, l0); split_bf16(v11, h1, l1);
                hp.x = h0; hp.y = h1; lp.x = l0; lp.y = l1;
                *(__nv_bfloat162*)&Cb3[rb1 + cA]          = hp;
                *(__nv_bfloat162*)&Cb3[rb1 + Nn + cA]     = hp;
                *(__nv_bfloat162*)&Cb3[rb1 + 2 * Nn + cA] = lp;
            }
        }
    }

    if (ATT) {
#pragma unroll
        for (int mi = 0; mi < 2; mi++) {
            const int rl0 = warp_m * 32 + mi * 16 + g;
            atomicAdd(&s_as[rl0], ssv[mi][0]);
            atomicAdd(&s_as[rl0 + 8], ssv[mi][1]);
            atomicAdd(&s_ad[rl0], sdv[mi][0]);
            atomicAdd(&s_ad[rl0 + 8], sdv[mi][1]);
        }
        __syncthreads();
        if (tid < 128) {
            const int head = (ATT == 2) ? (int)blockIdx.x : 0;
            const int row = row0 + tid;
            atts[row * heads + head] = s_as[tid];
            attd[row * heads + head] = s_ad[tid];
        }
    }
}

// ================= layer-1 aggregation (one-pass) =================
__global__ void __launch_bounds__(128) k_agg1(const float* __restrict__ b1) {
    const int n = blockIdx.x, tid = threadIdx.x;
    const int h = tid >> 5;
    const int beg = g_off[n], end = g_off[n + 1];

    __shared__ float s_ex[128 * 4];
    __shared__ int   s_s[128];

    const float4 ad = *(const float4*)&g_att1d[n * 4];

    float4 acc = make_float4(0.f, 0.f, 0.f, 0.f);
    float den = 0.f;
    for (int c0 = beg; c0 < end; c0 += 128) {
        int mcnt = min(128, end - c0);
        if (tid < mcnt) {
            int s = g_csrc[c0 + tid];
            s_s[tid] = s;
            float4 as = *(const float4*)&g_att1s[s * 4];
            s_ex[tid * 4 + 0] = expf(lrelu02(as.x + ad.x));
            s_ex[tid * 4 + 1] = expf(lrelu02(as.y + ad.y));
            s_ex[tid * 4 + 2] = expf(lrelu02(as.z + ad.z));
            s_ex[tid * 4 + 3] = expf(lrelu02(as.w + ad.w));
        }
        __syncthreads();
        for (int j = 0; j < mcnt; j++) {
            float w = s_ex[j * 4 + h];
            den += w;
            uint2 hv2 = *(const uint2*)&g_h1h[(size_t)s_s[j] * 512 + tid * 4];
            float2 f01 = __half22float2(*(const __half2*)&hv2.x);
            float2 f23 = __half22float2(*(const __half2*)&hv2.y);
            acc.x += f01.x * w; acc.y += f01.y * w;
            acc.z += f23.x * w; acc.w += f23.y * w;
        }
        __syncthreads();
    }
    const float invden = 1.f / den;
    float4 bv = *(const float4*)&b1[tid * 4];
    float o0 = eluf(acc.x * invden + bv.x), o1 = eluf(acc.y * invden + bv.y);
    float o2 = eluf(acc.z * invden + bv.z), o3 = eluf(acc.w * invden + bv.w);
    bf16 h0, l0, h1b, l1, h2b, l2, h3b, l3;
    split_bf16(o0, h0, l0); split_bf16(o1, h1b, l1);
    split_bf16(o2, h2b, l2); split_bf16(o3, h3b, l3);
    __nv_bfloat162 hA, hB, lA, lB;
    hA.x = h0; hA.y = h1b; hB.x = h2b; hB.y = h3b;
    lA.x = l0; lA.y = l1;  lB.x = l2;  lB.y = l3;
    const size_t rb = (size_t)n * 1536;
    const int cb = tid * 4;
    *(__nv_bfloat162*)&g_e1p[rb + cb]            = hA;
    *(__nv_bfloat162*)&g_e1p[rb + cb + 2]        = hB;
    *(__nv_bfloat162*)&g_e1p[rb + 512 + cb]      = hA;
    *(__nv_bfloat162*)&g_e1p[rb + 512 + cb + 2]  = hB;
    *(__nv_bfloat162*)&g_e1p[rb + 1024 + cb]     = lA;
    *(__nv_bfloat162*)&g_e1p[rb + 1024 + cb + 2] = lB;
}

// ================= layer-2 aggregation (one-pass) =================
__global__ void __launch_bounds__(128) k_agg2(const float* __restrict__ b2) {
    const int n = blockIdx.x, tid = threadIdx.x;
    const int beg = g_off[n], end = g_off[n + 1];

    __shared__ float s_ex[128];
    __shared__ int   s_s[128];

    const float adn = g_att2d[n];

    float acc = 0.f, den = 0.f;
    for (int c0 = beg; c0 < end; c0 += 128) {
        int mcnt = min(128, end - c0);
        if (tid < mcnt) {
            int s = g_csrc[c0 + tid];
            s_s[tid] = s;
            s_ex[tid] = expf(lrelu02(g_att2s[s] + adn));
        }
        __syncthreads();
        for (int j = 0; j < mcnt; j++) {
            float w = s_ex[j];
            den += w;
            acc += __half2float(g_h2h[(size_t)s_s[j] * 128 + tid]) * w;
        }
        __syncthreads();
    }
    float o = eluf(acc / den + b2[tid]);
    bf16 h, l;
    split_bf16(o, h, l);
    g_tp[(size_t)n * 384 + tid]       = h;
    g_tp[(size_t)n * 384 + 128 + tid] = h;
    g_tp[(size_t)n * 384 + 256 + tid] = l;
}

// ================= fused edge MLP =================
__global__ void __launch_bounds__(256) k_edge_final(const void* __restrict__ ei,
                                                    const float* __restrict__ eattr,
                                                    const float* __restrict__ We1,
                                                    const float* __restrict__ We2,
                                                    const float* __restrict__ be2,
                                                    float* __restrict__ out) {
    __shared__ float sW1[16 * 128];
    __shared__ float sW2[128 * 16];
    __shared__ float sHid[8][128];
    const int tid = threadIdx.x;
    for (int i = tid; i < 2048; i += 256) {
        sW1[i] = We1[256 * 128 + i];
        sW2[i] = We2[i];
    }
    const int is64 = g_is64;
    __syncthreads();

    const int warp = tid >> 5, lane = tid & 31;
    const long e = (long)blockIdx.x * 8 + warp;
    if (e < EE) {
        int s = idx_at(ei, e, is64);
        int d = idx_at(ei, (long)EE + e, is64);
        float4 p = *(const float4*)&g_PQ[(size_t)s * 256 + lane * 4];
        float4 q = *(const float4*)&g_PQ[(size_t)d * 256 + 128 + lane * 4];
        float4 hv;
        hv.x = p.x + q.x; hv.y = p.y + q.y; hv.z = p.z + q.z; hv.w = p.w + q.w;
        float eav = (lane < 16) ? eattr[e * 16 + lane] : 0.f;
#pragma unroll
        for (int k = 0; k < 16; k++) {
            float ek = __shfl_sync(0xffffffffu, eav, k);
            float4 wv = *(const float4*)&sW1[k * 128 + lane * 4];
            hv.x += ek * wv.x; hv.y += ek * wv.y;
            hv.z += ek * wv.z; hv.w += ek * wv.w;
        }
        hv.x = fmaxf(hv.x, 0.f); hv.y = fmaxf(hv.y, 0.f);
        hv.z = fmaxf(hv.z, 0.f); hv.w = fmaxf(hv.w, 0.f);
        *(float4*)&sHid[warp][lane * 4] = hv;
    }
    __syncwarp();
    if (e < EE) {
        const int o = lane & 15, half = lane >> 4;
        float acc = 0.f;
#pragma unroll
        for (int c = 0; c < 64; c++) {
            int cc = half * 64 + c;
            acc += sHid[warp][cc] * sW2[cc * 16 + o];
        }
        acc += __shfl_xor_sync(0xffffffffu, acc, 16);
        if (lane < 16) out[e * 16 + lane] = acc + be2[lane];
    }
}

// ================= launcher =================
extern "C" void kernel_launch(void* const* d_in, const int* in_sizes, int n_in,
                              void* d_out, int out_size) {
    const float* x    = (const float*)d_in[0];
    const void*  ei   = d_in[1];
    const float* eatt = (const float*)d_in[2];
    const float* W1   = (const float*)d_in[3];
    const float* as1  = (const float*)d_in[4];
    const float* ad1  = (const float*)d_in[5];
    const float* b1   = (const float*)d_in[6];
    const float* W2   = (const float*)d_in[7];
    const float* as2  = (const float*)d_in[8];
    const float* ad2  = (const float*)d_in[9];
    const float* b2   = (const float*)d_in[10];
    const float* Wo1  = (const float*)d_in[11];
    const float* bo1  = (const float*)d_in[12];
    const float* Wo2  = (const float*)d_in[13];
    const float* bo2  = (const float*)d_in[14];
    const float* We1  = (const float*)d_in[15];
    const float* be1  = (const float*)d_in[16];
    const float* We2  = (const float*)d_in[17];
    const float* be2  = (const float*)d_in[18];

    float* out  = (float*)d_out;
    float* xo   = out;
    float* eout = out + (size_t)NN * 128;

    bf16 *xp, *e1p, *tp, *up, *xop, *W1t, *W2t, *Wo1t, *Wo2t, *WePQt;
    __half *h1h, *h2h;
    float *PQ, *a1s, *a1d, *a2s, *a2d, *bePQ;
    cudaGetSymbolAddress((void**)&xp,  g_xp);
    cudaGetSymbolAddress((void**)&e1p, g_e1p);
    cudaGetSymbolAddress((void**)&tp,  g_tp);
    cudaGetSymbolAddress((void**)&up,  g_up);
    cudaGetSymbolAddress((void**)&xop, g_xop);
    cudaGetSymbolAddress((void**)&W1t, g_W1t);
    cudaGetSymbolAddress((void**)&W2t, g_W2t);
    cudaGetSymbolAddress((void**)&Wo1t, g_Wo1t);
    cudaGetSymbolAddress((void**)&Wo2t, g_Wo2t);
    cudaGetSymbolAddress((void**)&WePQt, g_WePQt);
    cudaGetSymbolAddress((void**)&h1h, g_h1h);
    cudaGetSymbolAddress((void**)&h2h, g_h2h);
    cudaGetSymbolAddress((void**)&PQ,  g_PQ);
    cudaGetSymbolAddress((void**)&bePQ, g_bePQ);
    cudaGetSymbolAddress((void**)&a1s, g_att1s);
    cudaGetSymbolAddress((void**)&a1d, g_att1d);
    cudaGetSymbolAddress((void**)&a2s, g_att2s);
    cudaGetSymbolAddress((void**)&a2d, g_att2d);

    // CSR build
    k_detect<<<1, 256>>>((const int*)ei);
    k_zero_deg<<<(NN + 255) / 256, 256>>>();
    k_hist<<<(ET + 255) / 256, 256>>>(ei);
    k_scan1<<<125, 256>>>();
    k_scan2<<<1, 128>>>();
    k_scan3<<<125, 256>>>();
    k_scatter<<<(ET + 255) / 256, 256>>>(ei);

    // conversions
    k_convA<<<(int)(((long)NN * 128 + 255) / 256), 256>>>(x, xp, 128, (long)NN * 128);
    k_convW<<<(128 * 512 + 255) / 256, 256>>>(W1, W1t, 128, 512);
    k_convW<<<(512 * 128 + 255) / 256, 256>>>(W2, W2t, 512, 128);
    k_convW<<<(128 * 128 + 255) / 256, 256>>>(Wo1, Wo1t, 128, 128);
    k_convW<<<(128 * 128 + 255) / 256, 256>>>(Wo2, Wo2t, 128, 128);
    k_convW<<<(128 * 128 + 255) / 256, 256>>>(We1, WePQt, 128, 128);
    k_convW<<<(128 * 128 + 255) / 256, 256>>>(We1 + 128 * 128, WePQt + 128 * 384, 128, 128);
    k_mkbias<<<1, 256>>>(be1);

    // layer 1 (att dots fused, h1 in fp16)
    k_mgemm<0, 2><<<dim3(4, 250), 256>>>(xp, W1t, 384, 512,
        nullptr, nullptr, h1h, nullptr, as1, ad1, a1s, a1d, 4);
    k_agg1<<<NN, 128>>>(b1);

    // layer 2 (h2 in fp16)
    k_mgemm<0, 1><<<dim3(1, 250), 256>>>(e1p, W2t, 1536, 128,
        nullptr, nullptr, h2h, nullptr, as2, ad2, a2s, a2d, 1);
    k_agg2<<<NN, 128>>>(b2);

    // output MLP
    k_mgemm<1, 0><<<dim3(1, 250), 256>>>(tp, Wo1t, 384, 128,
        bo1, nullptr, nullptr, up, nullptr, nullptr, nullptr, nullptr, 1);
    k_mgemm<0, 0><<<dim3(1, 250), 256>>>(up, Wo2t, 384, 128,
        bo2, xo, nullptr, xop, nullptr, nullptr, nullptr, nullptr, 1);

    // edge MLP decomposition: [P | Q] in one Nn=256 GEMM
    k_mgemm<0, 0><<<dim3(2, 250), 256>>>(xop, WePQt, 384, 256,
        bePQ, PQ, nullptr, nullptr, nullptr, nullptr, nullptr, nullptr, 1);
    k_edge_final<<<EE / 8, 256>>>(ei, eatt, We1, We2, be2, eout);
}

// round 6
// speedup vs baseline: 1.3764x; 1.0607x over previous
#include <cuda_runtime.h>
#include <cuda_bf16.h>
#include <cuda_fp16.h>
#include <cstdint>

#define NN 32000
#define EE 512000
#define ET (EE + NN)
#define DD 128
#define HH 4
#define EAD 16

typedef __nv_bfloat16 bf16;

// ================= scratch =================
__device__ int   g_is64;
__device__ int   g_deg[NN];
__device__ int   g_off[NN + 1];
__device__ int   g_cur[NN];
__device__ int   g_csrc[ET];
__device__ int   g_bsum[128];
__device__ int   g_boff[128];

__device__ __half g_h1h[(size_t)NN * 512];
__device__ __half g_h2h[(size_t)NN * 128];
__device__ float g_att1s[NN * 4];
__device__ float g_att1d[NN * 4];
__device__ float g_att2s[NN];
__device__ float g_att2d[NN];
__device__ float g_PQ[(size_t)NN * 256];
__device__ float g_bePQ[256];

// bf16 split activations: [hi | lo], pitch = 2*K
__device__ bf16  g_xp [(size_t)NN * 256];
__device__ bf16  g_e1p[(size_t)NN * 1024];
__device__ bf16  g_tp [(size_t)NN * 256];
__device__ bf16  g_up [(size_t)NN * 256];
__device__ bf16  g_xop[(size_t)NN * 256];
// bf16 split transposed weights: [N, 2K] = [hi | lo]
__device__ bf16  g_W1t  [512 * 256];
__device__ bf16  g_W2t  [128 * 1024];
__device__ bf16  g_Wo1t [128 * 256];
__device__ bf16  g_Wo2t [128 * 256];
__device__ bf16  g_WePQt[256 * 256];

// ================= helpers =================
__device__ __forceinline__ float lrelu02(float a) { return a > 0.f ? a : 0.2f * a; }
__device__ __forceinline__ float eluf(float v)    { return v > 0.f ? v : expm1f(v); }
__device__ __forceinline__ int idx_at(const void* ei, long pos, int is64) {
    if (is64) return (int)((const long long*)ei)[pos];
    return ((const int*)ei)[pos];
}
__device__ __forceinline__ void split_bf16(float v, bf16& h, bf16& l) {
    h = __float2bfloat16(v);
    l = __float2bfloat16(v - __bfloat162float(h));
}
__device__ __forceinline__ uint32_t smem_u32(const void* p) {
    uint32_t a;
    asm("{ .reg .u64 t; cvta.to.shared.u64 t, %1; cvt.u32.u64 %0, t; }" : "=r"(a) : "l"(p));
    return a;
}
__device__ __forceinline__ void cp_async16(uint32_t saddr, const void* g) {
    asm volatile("cp.async.cg.shared.global [%0], [%1], 16;" :: "r"(saddr), "l"(g));
}
__device__ __forceinline__ void mma_bf16(float* c, const uint32_t* a, const uint32_t* b) {
    asm volatile(
        "mma.sync.aligned.m16n8k16.row.col.f32.bf16.bf16.f32 "
        "{%0,%1,%2,%3}, {%4,%5,%6,%7}, {%8,%9}, {%0,%1,%2,%3};"
        : "+f"(c[0]), "+f"(c[1]), "+f"(c[2]), "+f"(c[3])
        : "r"(a[0]), "r"(a[1]), "r"(a[2]), "r"(a[3]), "r"(b[0]), "r"(b[1]));
}
__device__ __forceinline__ void ldm_x4(uint32_t* r, uint32_t addr) {
    asm volatile("ldmatrix.sync.aligned.m8n8.x4.shared.b16 {%0,%1,%2,%3}, [%4];"
                 : "=r"(r[0]), "=r"(r[1]), "=r"(r[2]), "=r"(r[3]) : "r"(addr));
}

// ================= CSR build =================
// grid 125 x 256: zero degrees; block 0 also detects dtype
__global__ void k_init(const int* w) {
    const int i = blockIdx.x * 256 + threadIdx.x;
    g_deg[i] = 0;
    if (blockIdx.x == 0) {
        __shared__ int s_any;
        if (threadIdx.x == 0) s_any = 0;
        __syncthreads();
        int any = 0;
        for (int j = threadIdx.x; j < 1024; j += 256) any |= w[2 * j + 1];
        if (any) atomicOr(&s_any, 1);
        __syncthreads();
        if (threadIdx.x == 0) g_is64 = (s_any == 0) ? 1 : 0;
    }
}
__global__ void k_hist(const void* ei) {
    int is64 = g_is64;
    long e = (long)blockIdx.x * blockDim.x + threadIdx.x;
    if (e >= ET) return;
    int d = (e < EE) ? idx_at(ei, (long)EE + e, is64) : (int)(e - EE);
    atomicAdd(&g_deg[d], 1);
}
__global__ void k_scan1() {
    __shared__ int s[256];
    const int tid = threadIdx.x;
    const int idx = blockIdx.x * 256 + tid;
    int v = g_deg[idx];
    s[tid] = v;
    __syncthreads();
#pragma unroll
    for (int off = 1; off < 256; off <<= 1) {
        int t = (tid >= off) ? s[tid - off] : 0;
        __syncthreads();
        s[tid] += t;
        __syncthreads();
    }
    g_off[idx] = s[tid] - v;
    if (tid == 255) g_bsum[blockIdx.x] = s[255];
}
__global__ void k_scan2() {
    __shared__ int s[128];
    const int tid = threadIdx.x;
    int v = (tid < 125) ? g_bsum[tid] : 0;
    s[tid] = v;
    __syncthreads();
#pragma unroll
    for (int off = 1; off < 128; off <<= 1) {
        int t = (tid >= off) ? s[tid - off] : 0;
        __syncthreads();
        s[tid] += t;
        __syncthreads();
    }
    if (tid < 125) g_boff[tid] = s[tid] - v;
    if (tid == 127) g_off[NN] = s[127];
}
__global__ void k_scan3() {
    const int idx = blockIdx.x * 256 + threadIdx.x;
    int o = g_off[idx] + g_boff[blockIdx.x];
    g_off[idx] = o;
    g_cur[idx] = o;
}
__global__ void k_scatter(const void* ei) {
    int is64 = g_is64;
    long e = (long)blockIdx.x * blockDim.x + threadIdx.x;
    if (e >= ET) return;
    int s, d;
    if (e < EE) {
        s = idx_at(ei, e, is64);
        d = idx_at(ei, (long)EE + e, is64);
    } else {
        s = d = (int)(e - EE);
    }
    int pos = atomicAdd(&g_cur[d], 1);
    g_csrc[pos] = s;
}

// ================= conversions =================
__global__ void k_convA(const float* __restrict__ src, bf16* __restrict__ dst, int K, long total) {
    long i = (long)blockIdx.x * blockDim.x + threadIdx.x;
    if (i >= total) return;
    long m = i / K;
    int  k = (int)(i - m * K);
    bf16 h, l;
    split_bf16(src[i], h, l);
    bf16* row = dst + m * 2 * K;
    row[k] = h; row[K + k] = l;
}
__device__ __forceinline__ void conv_emit(const float* W, bf16* Wt, int K, int N, int idx) {
    int n = idx / K;
    int k = idx - n * K;
    bf16 h, l;
    split_bf16(W[(size_t)k * N + n], h, l);
    bf16* row = Wt + (size_t)n * 2 * K;
    row[k] = h; row[K + k] = l;
}
// one kernel for all weight conversions + PQ bias. grid 770 x 256.
__global__ void k_convWall(const float* W1, const float* W2,
                           const float* Wo1, const float* Wo2,
                           const float* We1, const float* be1) {
    int i = blockIdx.x * 256 + threadIdx.x;
    if (i < 65536)          conv_emit(W1,  g_W1t,  128, 512, i);
    else if (i < 131072)    conv_emit(W2,  g_W2t,  512, 128, i - 65536);
    else if (i < 147456)    conv_emit(Wo1, g_Wo1t, 128, 128, i - 131072);
    else if (i < 163840)    conv_emit(Wo2, g_Wo2t, 128, 128, i - 147456);
    else if (i < 180224)    conv_emit(We1, g_WePQt, 128, 128, i - 163840);
    else if (i < 196608)    conv_emit(We1 + 128 * 128, g_WePQt + 128 * 256, 128, 128, i - 180224);
    else if (i < 196864) {
        int j = i - 196608;
        g_bePQ[j] = (j < 128) ? be1[j] : 0.f;
    }
}

// ================= mma.sync 2-term split-bf16 GEMM =================
// C = act( A.B^T + bias ) with A,B stored [hi|lo] pitch 2K.
// D = Ah.Bh + Ah.Bl + Al.Bh (fp32 accum). Tile 128x128, k-step 16,
// 256 threads = 8 warps (4m x 2n), warp tile 32x64.
// ACT: 0 none, 1 relu.  ATT: 0 none, 1 head0, 2 head=blockIdx.x
template <int ACT, int ATT>
__global__ void __launch_bounds__(256) k_mgemm(
    const bf16* __restrict__ Ap, const bf16* __restrict__ Bp,
    int K, int Nn,
    const float* __restrict__ bias,
    float* __restrict__ Cf, __half* __restrict__ Ch, bf16* __restrict__ Cb2,
    const float* __restrict__ a_s, const float* __restrict__ a_d,
    float* __restrict__ atts, float* __restrict__ attd, int heads)
{
    __shared__ bf16 As[2][128][40];   // cols 0..15 hi, 16..31 lo, 32..39 pad
    __shared__ bf16 Bs[2][128][40];
    __shared__ float s_as[128], s_ad[128];

    const int tid = threadIdx.x;
    const int wid = tid >> 5, lane = tid & 31;
    const int g = lane >> 2, tig = lane & 3;
    const int warp_m = wid & 3, warp_n = wid >> 2;
    const int row0 = blockIdx.y * 128, col0 = blockIdx.x * 128;
    const int K2 = 2 * K;

    // loaders: 2 threads per row; lsel 0 -> hi half (bytes 0..31), 1 -> lo (32..63)
    const int lrow = tid >> 1, lsel = tid & 1;
    const bf16* Agb = Ap + (size_t)(row0 + lrow) * K2 + lsel * K;
    const bf16* Bgb = Bp + (size_t)(col0 + lrow) * K2 + lsel * K;
    const uint32_t sA = smem_u32(&As[0][0][0]);
    const uint32_t sB = smem_u32(&Bs[0][0][0]);
    const uint32_t soff = (uint32_t)lrow * 80u + (uint32_t)lsel * 32u;

    const int arow_l = (((lane >> 3) & 1) << 3) + (lane & 7);
    const int acol_l = (lane >> 4) << 3;
    const int brow_l = (lane & 7) + ((lane >> 4) << 3);
    const int bcol_l = ((lane >> 3) & 1) << 3;

    float c[2][8][4];
#pragma unroll
    for (int i = 0; i < 2; i++)
#pragma unroll
        for (int j = 0; j < 8; j++)
#pragma unroll
            for (int q = 0; q < 4; q++) c[i][j][q] = 0.f;

    cp_async16(sA + soff, Agb);
    cp_async16(sA + soff + 16, Agb + 8);
    cp_async16(sB + soff, Bgb);
    cp_async16(sB + soff + 16, Bgb + 8);
    asm volatile("cp.async.commit_group;" ::: "memory");

    const int NT = K >> 4;
    for (int kt = 0; kt < NT; kt++) {
        const int buf = kt & 1;
        if (kt + 1 < NT) {
            const int koff = (kt + 1) * 16;
            const uint32_t bofs = ((kt + 1) & 1) ? 10240u : 0u;
            cp_async16(sA + bofs + soff, Agb + koff);
            cp_async16(sA + bofs + soff + 16, Agb + koff + 8);
            cp_async16(sB + bofs + soff, Bgb + koff);
            cp_async16(sB + bofs + soff + 16, Bgb + koff + 8);
            asm volatile("cp.async.commit_group;" ::: "memory");
            asm volatile("cp.async.wait_group 1;" ::: "memory");
        } else {
            asm volatile("cp.async.wait_group 0;" ::: "memory");
        }
        __syncthreads();

        const uint32_t sAb = sA + (uint32_t)buf * 10240u;
        const uint32_t sBb = sB + (uint32_t)buf * 10240u;

        uint32_t ah[2][4], al[2][4], bb[8][2];
#pragma unroll
        for (int mi = 0; mi < 2; mi++) {
            uint32_t r = sAb + (uint32_t)(warp_m * 32 + mi * 16 + arow_l) * 80u
                             + (uint32_t)acol_l * 2u;
            ldm_x4(ah[mi], r);
            ldm_x4(al[mi], r + 32u);
        }
        // b hi
#pragma unroll
        for (int p = 0; p < 4; p++) {
            uint32_t t[4];
            uint32_t r = sBb + (uint32_t)(warp_n * 64 + p * 16 + brow_l) * 80u
                             + (uint32_t)bcol_l * 2u;
            ldm_x4(t, r);
            bb[2 * p][0] = t[0]; bb[2 * p][1] = t[1];
            bb[2 * p + 1][0] = t[2]; bb[2 * p + 1][1] = t[3];
        }
#pragma unroll
        for (int mi = 0; mi < 2; mi++)
#pragma unroll
            for (int ni = 0; ni < 8; ni++)
                mma_bf16(c[mi][ni], ah[mi], bb[ni]);
#pragma unroll
        for (int mi = 0; mi < 2; mi++)
#pragma unroll
            for (int ni = 0; ni < 8; ni++)
                mma_bf16(c[mi][ni], al[mi], bb[ni]);
        // b lo
#pragma unroll
        for (int p = 0; p < 4; p++) {
            uint32_t t[4];
            uint32_t r = sBb + (uint32_t)(warp_n * 64 + p * 16 + brow_l) * 80u
                             + (uint32_t)bcol_l * 2u + 32u;
            ldm_x4(t, r);
            bb[2 * p][0] = t[0]; bb[2 * p][1] = t[1];
            bb[2 * p + 1][0] = t[2]; bb[2 * p + 1][1] = t[3];
        }
#pragma unroll
        for (int mi = 0; mi < 2; mi++)
#pragma unroll
            for (int ni = 0; ni < 8; ni++)
                mma_bf16(c[mi][ni], ah[mi], bb[ni]);
        __syncthreads();
    }

    if (ATT) {
        if (tid < 128) { s_as[tid] = 0.f; s_ad[tid] = 0.f; }
        __syncthreads();
    }

    float ssv[2][2] = {{0.f, 0.f}, {0.f, 0.f}};
    float sdv[2][2] = {{0.f, 0.f}, {0.f, 0.f}};

#pragma unroll
    for (int ni = 0; ni < 8; ni++) {
        const int cA = col0 + warp_n * 64 + ni * 8 + tig * 2;
        float b0 = 0.f, b1 = 0.f;
        if (bias) { b0 = __ldg(&bias[cA]); b1 = __ldg(&bias[cA + 1]); }
        float asA = 0.f, asB = 0.f, adA = 0.f, adB = 0.f;
        if (ATT) {
            asA = __ldg(&a_s[cA]); asB = __ldg(&a_s[cA + 1]);
            adA = __ldg(&a_d[cA]); adB = __ldg(&a_d[cA + 1]);
        }
#pragma unroll
        for (int mi = 0; mi < 2; mi++) {
            const int r0g = row0 + warp_m * 32 + mi * 16 + g;
            const int r1g = r0g + 8;
            float v00 = c[mi][ni][0] + b0, v01 = c[mi][ni][1] + b1;
            float v10 = c[mi][ni][2] + b0, v11 = c[mi][ni][3] + b1;
            if (ACT == 1) {
                v00 = fmaxf(v00, 0.f); v01 = fmaxf(v01, 0.f);
                v10 = fmaxf(v10, 0.f); v11 = fmaxf(v11, 0.f);
            }
            if (ATT) {
                ssv[mi][0] += v00 * asA + v01 * asB;
                ssv[mi][1] += v10 * asA + v11 * asB;
                sdv[mi][0] += v00 * adA + v01 * adB;
                sdv[mi][1] += v10 * adA + v11 * adB;
            }
            if (Cf) {
                *(float2*)&Cf[(size_t)r0g * Nn + cA] = make_float2(v00, v01);
                *(float2*)&Cf[(size_t)r1g * Nn + cA] = make_float2(v10, v11);
            }
            if (Ch) {
                *(__half2*)&Ch[(size_t)r0g * Nn + cA] = __floats2half2_rn(v00, v01);
                *(__half2*)&Ch[(size_t)r1g * Nn + cA] = __floats2half2_rn(v10, v11);
            }
            if (Cb2) {
                bf16 h0, l0, h1, l1;
                __nv_bfloat162 hp, lp;
                size_t rb0 = (size_t)r0g * 2 * Nn;
                split_bf16(v00, h0, l0); split_bf16(v01, h1, l1);
                hp.x = h0; hp.y = h1; lp.x = l0; lp.y = l1;
                *(__nv_bfloat162*)&Cb2[rb0 + cA]      = hp;
                *(__nv_bfloat162*)&Cb2[rb0 + Nn + cA] = lp;
                size_t rb1 = (size_t)r1g * 2 * Nn;
                split_bf16(v10, h0, l0); split_bf16(v11, h1, l1);
                hp.x = h0; hp.y = h1; lp.x = l0; lp.y = l1;
                *(__nv_bfloat162*)&Cb2[rb1 + cA]      = hp;
                *(__nv_bfloat162*)&Cb2[rb1 + Nn + cA] = lp;
            }
        }
    }

    if (ATT) {
#pragma unroll
        for (int mi = 0; mi < 2; mi++) {
            const int rl0 = warp_m * 32 + mi * 16 + g;
            atomicAdd(&s_as[rl0], ssv[mi][0]);
            atomicAdd(&s_as[rl0 + 8], ssv[mi][1]);
            atomicAdd(&s_ad[rl0], sdv[mi][0]);
            atomicAdd(&s_ad[rl0 + 8], sdv[mi][1]);
        }
        __syncthreads();
        if (tid < 128) {
            const int head = (ATT == 2) ? (int)blockIdx.x : 0;
            const int row = row0 + tid;
            atts[row * heads + head] = s_as[tid];
            attd[row * heads + head] = s_ad[tid];
        }
    }
}

// ================= layer-1 aggregation (one-pass) =================
__global__ void __launch_bounds__(128) k_agg1(const float* __restrict__ b1) {
    const int n = blockIdx.x, tid = threadIdx.x;
    const int h = tid >> 5;
    const int beg = g_off[n], end = g_off[n + 1];

    __shared__ float s_ex[128 * 4];
    __shared__ int   s_s[128];

    const float4 ad = *(const float4*)&g_att1d[n * 4];

    float4 acc = make_float4(0.f, 0.f, 0.f, 0.f);
    float den = 0.f;
    for (int c0 = beg; c0 < end; c0 += 128) {
        int mcnt = min(128, end - c0);
        if (tid < mcnt) {
            int s = g_csrc[c0 + tid];
            s_s[tid] = s;
            float4 as = *(const float4*)&g_att1s[s * 4];
            s_ex[tid * 4 + 0] = expf(lrelu02(as.x + ad.x));
            s_ex[tid * 4 + 1] = expf(lrelu02(as.y + ad.y));
            s_ex[tid * 4 + 2] = expf(lrelu02(as.z + ad.z));
            s_ex[tid * 4 + 3] = expf(lrelu02(as.w + ad.w));
        }
        __syncthreads();
        for (int j = 0; j < mcnt; j++) {
            float w = s_ex[j * 4 + h];
            den += w;
            uint2 hv2 = *(const uint2*)&g_h1h[(size_t)s_s[j] * 512 + tid * 4];
            float2 f01 = __half22float2(*(const __half2*)&hv2.x);
            float2 f23 = __half22float2(*(const __half2*)&hv2.y);
            acc.x += f01.x * w; acc.y += f01.y * w;
            acc.z += f23.x * w; acc.w += f23.y * w;
        }
        __syncthreads();
    }
    const float invden = 1.f / den;
    float4 bv = *(const float4*)&b1[tid * 4];
    float o0 = eluf(acc.x * invden + bv.x), o1 = eluf(acc.y * invden + bv.y);
    float o2 = eluf(acc.z * invden + bv.z), o3 = eluf(acc.w * invden + bv.w);
    bf16 h0, l0, h1b, l1, h2b, l2, h3b, l3;
    split_bf16(o0, h0, l0); split_bf16(o1, h1b, l1);
    split_bf16(o2, h2b, l2); split_bf16(o3, h3b, l3);
    __nv_bfloat162 hA, hB, lA, lB;
    hA.x = h0; hA.y = h1b; hB.x = h2b; hB.y = h3b;
    lA.x = l0; lA.y = l1;  lB.x = l2;  lB.y = l3;
    const size_t rb = (size_t)n * 1024;
    const int cb = tid * 4;
    *(__nv_bfloat162*)&g_e1p[rb + cb]           = hA;
    *(__nv_bfloat162*)&g_e1p[rb + cb + 2]       = hB;
    *(__nv_bfloat162*)&g_e1p[rb + 512 + cb]     = lA;
    *(__nv_bfloat162*)&g_e1p[rb + 512 + cb + 2] = lB;
}

// ================= layer-2 aggregation (one-pass) =================
__global__ void __launch_bounds__(128) k_agg2(const float* __restrict__ b2) {
    const int n = blockIdx.x, tid = threadIdx.x;
    const int beg = g_off[n], end = g_off[n + 1];

    __shared__ float s_ex[128];
    __shared__ int   s_s[128];

    const float adn = g_att2d[n];

    float acc = 0.f, den = 0.f;
    for (int c0 = beg; c0 < end; c0 += 128) {
        int mcnt = min(128, end - c0);
        if (tid < mcnt) {
            int s = g_csrc[c0 + tid];
            s_s[tid] = s;
            s_ex[tid] = expf(lrelu02(g_att2s[s] + adn));
        }
        __syncthreads();
        for (int j = 0; j < mcnt; j++) {
            float w = s_ex[j];
            den += w;
            acc += __half2float(g_h2h[(size_t)s_s[j] * 128 + tid]) * w;
        }
        __syncthreads();
    }
    float o = eluf(acc / den + b2[tid]);
    bf16 h, l;
    split_bf16(o, h, l);
    g_tp[(size_t)n * 256 + tid]       = h;
    g_tp[(size_t)n * 256 + 128 + tid] = l;
}

// ================= fused edge MLP =================
__global__ void __launch_bounds__(256) k_edge_final(const void* __restrict__ ei,
                                                    const float* __restrict__ eattr,
                                                    const float* __restrict__ We1,
                                                    const float* __restrict__ We2,
                                                    const float* __restrict__ be2,
                                                    float* __restrict__ out) {
    __shared__ float sW1[16 * 128];
    __shared__ float sW2[128 * 16];
    __shared__ float sHid[8][128];
    const int tid = threadIdx.x;
    for (int i = tid; i < 2048; i += 256) {
        sW1[i] = We1[256 * 128 + i];
        sW2[i] = We2[i];
    }
    const int is64 = g_is64;
    __syncthreads();

    const int warp = tid >> 5, lane = tid & 31;
    const long e = (long)blockIdx.x * 8 + warp;
    if (e < EE) {
        int s = idx_at(ei, e, is64);
        int d = idx_at(ei, (long)EE + e, is64);
        float4 p = *(const float4*)&g_PQ[(size_t)s * 256 + lane * 4];
        float4 q = *(const float4*)&g_PQ[(size_t)d * 256 + 128 + lane * 4];
        float4 hv;
        hv.x = p.x + q.x; hv.y = p.y + q.y; hv.z = p.z + q.z; hv.w = p.w + q.w;
        float eav = (lane < 16) ? eattr[e * 16 + lane] : 0.f;
#pragma unroll
        for (int k = 0; k < 16; k++) {
            float ek = __shfl_sync(0xffffffffu, eav, k);
            float4 wv = *(const float4*)&sW1[k * 128 + lane * 4];
            hv.x += ek * wv.x; hv.y += ek * wv.y;
            hv.z += ek * wv.z; hv.w += ek * wv.w;
        }
        hv.x = fmaxf(hv.x, 0.f); hv.y = fmaxf(hv.y, 0.f);
        hv.z = fmaxf(hv.z, 0.f); hv.w = fmaxf(hv.w, 0.f);
        *(float4*)&sHid[warp][lane * 4] = hv;
    }
    __syncwarp();
    if (e < EE) {
        // half h walks channels of parity h -> sW2 banks {o} vs {16+o}: conflict-free
        const int o = lane & 15, half = lane >> 4;
        float acc = 0.f;
#pragma unroll
        for (int c = 0; c < 64; c++) {
            int cc = half + 2 * c;
            acc += sHid[warp][cc] * sW2[cc * 16 + o];
        }
        acc += __shfl_xor_sync(0xffffffffu, acc, 16);
        if (lane < 16) out[e * 16 + lane] = acc + be2[lane];
    }
}

// ================= launcher =================
extern "C" void kernel_launch(void* const* d_in, const int* in_sizes, int n_in,
                              void* d_out, int out_size) {
    const float* x    = (const float*)d_in[0];
    const void*  ei   = d_in[1];
    const float* eatt = (const float*)d_in[2];
    const float* W1   = (const float*)d_in[3];
    const float* as1  = (const float*)d_in[4];
    const float* ad1  = (const float*)d_in[5];
    const float* b1   = (const float*)d_in[6];
    const float* W2   = (const float*)d_in[7];
    const float* as2  = (const float*)d_in[8];
    const float* ad2  = (const float*)d_in[9];
    const float* b2   = (const float*)d_in[10];
    const float* Wo1  = (const float*)d_in[11];
    const float* bo1  = (const float*)d_in[12];
    const float* Wo2  = (const float*)d_in[13];
    const float* bo2  = (const float*)d_in[14];
    const float* We1  = (const float*)d_in[15];
    const float* be1  = (const float*)d_in[16];
    const float* We2  = (const float*)d_in[17];
    const float* be2  = (const float*)d_in[18];

    float* out  = (float*)d_out;
    float* xo   = out;
    float* eout = out + (size_t)NN * 128;

    bf16 *xp, *e1p, *tp, *up, *xop, *W1t, *W2t, *Wo1t, *Wo2t, *WePQt;
    __half *h1h, *h2h;
    float *PQ, *a1s, *a1d, *a2s, *a2d, *bePQ;
    cudaGetSymbolAddress((void**)&xp,  g_xp);
    cudaGetSymbolAddress((void**)&e1p, g_e1p);
    cudaGetSymbolAddress((void**)&tp,  g_tp);
    cudaGetSymbolAddress((void**)&up,  g_up);
    cudaGetSymbolAddress((void**)&xop, g_xop);
    cudaGetSymbolAddress((void**)&W1t, g_W1t);
    cudaGetSymbolAddress((void**)&W2t, g_W2t);
    cudaGetSymbolAddress((void**)&Wo1t, g_Wo1t);
    cudaGetSymbolAddress((void**)&Wo2t, g_Wo2t);
    cudaGetSymbolAddress((void**)&WePQt, g_WePQt);
    cudaGetSymbolAddress((void**)&h1h, g_h1h);
    cudaGetSymbolAddress((void**)&h2h, g_h2h);
    cudaGetSymbolAddress((void**)&PQ,  g_PQ);
    cudaGetSymbolAddress((void**)&bePQ, g_bePQ);
    cudaGetSymbolAddress((void**)&a1s, g_att1s);
    cudaGetSymbolAddress((void**)&a1d, g_att1d);
    cudaGetSymbolAddress((void**)&a2s, g_att2s);
    cudaGetSymbolAddress((void**)&a2d, g_att2d);

    // CSR build
    k_init<<<125, 256>>>((const int*)ei);
    k_hist<<<(ET + 255) / 256, 256>>>(ei);
    k_scan1<<<125, 256>>>();
    k_scan2<<<1, 128>>>();
    k_scan3<<<125, 256>>>();
    k_scatter<<<(ET + 255) / 256, 256>>>(ei);

    // conversions
    k_convA<<<(int)(((long)NN * 128 + 255) / 256), 256>>>(x, xp, 128, (long)NN * 128);
    k_convWall<<<770, 256>>>(W1, W2, Wo1, Wo2, We1, be1);

    // layer 1 (att dots fused, h1 in fp16)
    k_mgemm<0, 2><<<dim3(4, 250), 256>>>(xp, W1t, 128, 512,
        nullptr, nullptr, h1h, nullptr, as1, ad1, a1s, a1d, 4);
    k_agg1<<<NN, 128>>>(b1);

    // layer 2 (h2 in fp16)
    k_mgemm<0, 1><<<dim3(1, 250), 256>>>(e1p, W2t, 512, 128,
        nullptr, nullptr, h2h, nullptr, as2, ad2, a2s, a2d, 1);
    k_agg2<<<NN, 128>>>(b2);

    // output MLP
    k_mgemm<1, 0><<<dim3(1, 250), 256>>>(tp, Wo1t, 128, 128,
        bo1, nullptr, nullptr, up, nullptr, nullptr, nullptr, nullptr, 1);
    k_mgemm<0, 0><<<dim3(1, 250), 256>>>(up, Wo2t, 128, 128,
        bo2, xo, nullptr, xop, nullptr, nullptr, nullptr, nullptr, 1);

    // edge MLP decomposition: [P | Q] in one Nn=256 GEMM
    k_mgemm<0, 0><<<dim3(2, 250), 256>>>(xop, WePQt, 128, 256,
        bePQ, PQ, nullptr, nullptr, nullptr, nullptr, nullptr, nullptr, 1);
    k_edge_final<<<EE / 8, 256>>>(ei, eatt, We1, We2, be2, eout);
}

// round 7
// speedup vs baseline: 1.4293x; 1.0384x over previous
#include <cuda_runtime.h>
#include <cuda_bf16.h>
#include <cuda_fp16.h>
#include <cstdint>

#define NN 32000
#define EE 512000
#define ET (EE + NN)
#define DD 128
#define HH 4
#define EAD 16

typedef __nv_bfloat16 bf16;

// ================= scratch =================
__device__ int   g_is64;
__device__ int   g_deg[NN];
__device__ int   g_off[NN + 1];
__device__ int   g_cur[NN];
__device__ int   g_csrc[ET];
__device__ int   g_bsum[128];
__device__ int   g_boff[128];

__device__ __half g_h1h[(size_t)NN * 512];
__device__ __half g_h2h[(size_t)NN * 128];
__device__ __half g_PQh[(size_t)NN * 256];   // [P | Q] per node, fp16
__device__ float g_att1s[NN * 4];
__device__ float g_att1d[NN * 4];
__device__ float g_att2s[NN];
__device__ float g_att2d[NN];
__device__ float g_bePQ[256];

// bf16 split activations: [hi | lo], pitch = 2*K
__device__ bf16  g_xp [(size_t)NN * 256];
__device__ bf16  g_e1p[(size_t)NN * 1024];
__device__ bf16  g_tp [(size_t)NN * 256];
// bf16 split transposed weights: [N, 2K] = [hi | lo]
__device__ bf16  g_W1t  [512 * 256];
__device__ bf16  g_W2t  [128 * 1024];
__device__ bf16  g_Wo1t [128 * 256];
__device__ bf16  g_Wo2t [128 * 256];
__device__ bf16  g_WePQt[256 * 256];

// ================= helpers =================
__device__ __forceinline__ float lrelu02(float a) { return a > 0.f ? a : 0.2f * a; }
__device__ __forceinline__ float eluf(float v)    { return v > 0.f ? v : expm1f(v); }
__device__ __forceinline__ int idx_at(const void* ei, long pos, int is64) {
    if (is64) return (int)((const long long*)ei)[pos];
    return ((const int*)ei)[pos];
}
__device__ __forceinline__ void split_bf16(float v, bf16& h, bf16& l) {
    h = __float2bfloat16(v);
    l = __float2bfloat16(v - __bfloat162float(h));
}
__device__ __forceinline__ uint32_t smem_u32(const void* p) {
    uint32_t a;
    asm("{ .reg .u64 t; cvta.to.shared.u64 t, %1; cvt.u32.u64 %0, t; }" : "=r"(a) : "l"(p));
    return a;
}
__device__ __forceinline__ void cp_async16(uint32_t saddr, const void* g) {
    asm volatile("cp.async.cg.shared.global [%0], [%1], 16;" :: "r"(saddr), "l"(g));
}
__device__ __forceinline__ void mma_bf16(float* c, const uint32_t* a, const uint32_t* b) {
    asm volatile(
        "mma.sync.aligned.m16n8k16.row.col.f32.bf16.bf16.f32 "
        "{%0,%1,%2,%3}, {%4,%5,%6,%7}, {%8,%9}, {%0,%1,%2,%3};"
        : "+f"(c[0]), "+f"(c[1]), "+f"(c[2]), "+f"(c[3])
        : "r"(a[0]), "r"(a[1]), "r"(a[2]), "r"(a[3]), "r"(b[0]), "r"(b[1]));
}
__device__ __forceinline__ void ldm_x4(uint32_t* r, uint32_t addr) {
    asm volatile("ldmatrix.sync.aligned.m8n8.x4.shared.b16 {%0,%1,%2,%3}, [%4];"
                 : "=r"(r[0]), "=r"(r[1]), "=r"(r[2]), "=r"(r[3]) : "r"(addr));
}

// ================= CSR build =================
__global__ void k_init(const int* w) {
    const int i = blockIdx.x * 256 + threadIdx.x;
    g_deg[i] = 0;
    if (blockIdx.x == 0) {
        __shared__ int s_any;
        if (threadIdx.x == 0) s_any = 0;
        __syncthreads();
        int any = 0;
        for (int j = threadIdx.x; j < 1024; j += 256) any |= w[2 * j + 1];
        if (any) atomicOr(&s_any, 1);
        __syncthreads();
        if (threadIdx.x == 0) g_is64 = (s_any == 0) ? 1 : 0;
    }
}
__global__ void k_hist(const void* ei) {
    int is64 = g_is64;
    long e = (long)blockIdx.x * blockDim.x + threadIdx.x;
    if (e >= ET) return;
    int d = (e < EE) ? idx_at(ei, (long)EE + e, is64) : (int)(e - EE);
    atomicAdd(&g_deg[d], 1);
}
__global__ void k_scan1() {
    __shared__ int s[256];
    const int tid = threadIdx.x;
    const int idx = blockIdx.x * 256 + tid;
    int v = g_deg[idx];
    s[tid] = v;
    __syncthreads();
#pragma unroll
    for (int off = 1; off < 256; off <<= 1) {
        int t = (tid >= off) ? s[tid - off] : 0;
        __syncthreads();
        s[tid] += t;
        __syncthreads();
    }
    g_off[idx] = s[tid] - v;
    if (tid == 255) g_bsum[blockIdx.x] = s[255];
}
__global__ void k_scan2() {
    __shared__ int s[128];
    const int tid = threadIdx.x;
    int v = (tid < 125) ? g_bsum[tid] : 0;
    s[tid] = v;
    __syncthreads();
#pragma unroll
    for (int off = 1; off < 128; off <<= 1) {
        int t = (tid >= off) ? s[tid - off] : 0;
        __syncthreads();
        s[tid] += t;
        __syncthreads();
    }
    if (tid < 125) g_boff[tid] = s[tid] - v;
    if (tid == 127) g_off[NN] = s[127];
}
__global__ void k_scan3() {
    const int idx = blockIdx.x * 256 + threadIdx.x;
    int o = g_off[idx] + g_boff[blockIdx.x];
    g_off[idx] = o;
    g_cur[idx] = o;
}
__global__ void k_scatter(const void* ei) {
    int is64 = g_is64;
    long e = (long)blockIdx.x * blockDim.x + threadIdx.x;
    if (e >= ET) return;
    int s, d;
    if (e < EE) {
        s = idx_at(ei, e, is64);
        d = idx_at(ei, (long)EE + e, is64);
    } else {
        s = d = (int)(e - EE);
    }
    int pos = atomicAdd(&g_cur[d], 1);
    g_csrc[pos] = s;
}

// ================= conversions =================
__global__ void k_convA(const float* __restrict__ src, bf16* __restrict__ dst, int K, long total) {
    long i = (long)blockIdx.x * blockDim.x + threadIdx.x;
    if (i >= total) return;
    long m = i / K;
    int  k = (int)(i - m * K);
    bf16 h, l;
    split_bf16(src[i], h, l);
    bf16* row = dst + m * 2 * K;
    row[k] = h; row[K + k] = l;
}
__device__ __forceinline__ void conv_emit(const float* W, bf16* Wt, int K, int N, int idx) {
    int n = idx / K;
    int k = idx - n * K;
    bf16 h, l;
    split_bf16(W[(size_t)k * N + n], h, l);
    bf16* row = Wt + (size_t)n * 2 * K;
    row[k] = h; row[K + k] = l;
}
__global__ void k_convWall(const float* W1, const float* W2,
                           const float* Wo1, const float* Wo2,
                           const float* We1, const float* be1) {
    int i = blockIdx.x * 256 + threadIdx.x;
    if (i < 65536)          conv_emit(W1,  g_W1t,  128, 512, i);
    else if (i < 131072)    conv_emit(W2,  g_W2t,  512, 128, i - 65536);
    else if (i < 147456)    conv_emit(Wo1, g_Wo1t, 128, 128, i - 131072);
    else if (i < 163840)    conv_emit(Wo2, g_Wo2t, 128, 128, i - 147456);
    else if (i < 180224)    conv_emit(We1, g_WePQt, 128, 128, i - 163840);
    else if (i < 196608)    conv_emit(We1 + 128 * 128, g_WePQt + 128 * 256, 128, 128, i - 180224);
    else if (i < 196864) {
        int j = i - 196608;
        g_bePQ[j] = (j < 128) ? be1[j] : 0.f;
    }
}

// ================= mma.sync 2-term split-bf16 GEMM =================
template <int ACT, int ATT>
__global__ void __launch_bounds__(256) k_mgemm(
    const bf16* __restrict__ Ap, const bf16* __restrict__ Bp,
    int K, int Nn,
    const float* __restrict__ bias,
    float* __restrict__ Cf, __half* __restrict__ Ch,
    const float* __restrict__ a_s, const float* __restrict__ a_d,
    float* __restrict__ atts, float* __restrict__ attd, int heads)
{
    __shared__ bf16 As[2][128][40];
    __shared__ bf16 Bs[2][128][40];
    __shared__ float s_as[128], s_ad[128];

    const int tid = threadIdx.x;
    const int wid = tid >> 5, lane = tid & 31;
    const int g = lane >> 2, tig = lane & 3;
    const int warp_m = wid & 3, warp_n = wid >> 2;
    const int row0 = blockIdx.y * 128, col0 = blockIdx.x * 128;
    const int K2 = 2 * K;

    const int lrow = tid >> 1, lsel = tid & 1;
    const bf16* Agb = Ap + (size_t)(row0 + lrow) * K2 + lsel * K;
    const bf16* Bgb = Bp + (size_t)(col0 + lrow) * K2 + lsel * K;
    const uint32_t sA = smem_u32(&As[0][0][0]);
    const uint32_t sB = smem_u32(&Bs[0][0][0]);
    const uint32_t soff = (uint32_t)lrow * 80u + (uint32_t)lsel * 32u;

    const int arow_l = (((lane >> 3) & 1) << 3) + (lane & 7);
    const int acol_l = (lane >> 4) << 3;
    const int brow_l = (lane & 7) + ((lane >> 4) << 3);
    const int bcol_l = ((lane >> 3) & 1) << 3;

    float c[2][8][4];
#pragma unroll
    for (int i = 0; i < 2; i++)
#pragma unroll
        for (int j = 0; j < 8; j++)
#pragma unroll
            for (int q = 0; q < 4; q++) c[i][j][q] = 0.f;

    cp_async16(sA + soff, Agb);
    cp_async16(sA + soff + 16, Agb + 8);
    cp_async16(sB + soff, Bgb);
    cp_async16(sB + soff + 16, Bgb + 8);
    asm volatile("cp.async.commit_group;" ::: "memory");

    const int NT = K >> 4;
    for (int kt = 0; kt < NT; kt++) {
        const int buf = kt & 1;
        if (kt + 1 < NT) {
            const int koff = (kt + 1) * 16;
            const uint32_t bofs = ((kt + 1) & 1) ? 10240u : 0u;
            cp_async16(sA + bofs + soff, Agb + koff);
            cp_async16(sA + bofs + soff + 16, Agb + koff + 8);
            cp_async16(sB + bofs + soff, Bgb + koff);
            cp_async16(sB + bofs + soff + 16, Bgb + koff + 8);
            asm volatile("cp.async.commit_group;" ::: "memory");
            asm volatile("cp.async.wait_group 1;" ::: "memory");
        } else {
            asm volatile("cp.async.wait_group 0;" ::: "memory");
        }
        __syncthreads();

        const uint32_t sAb = sA + (uint32_t)buf * 10240u;
        const uint32_t sBb = sB + (uint32_t)buf * 10240u;

        uint32_t ah[2][4], al[2][4], bb[8][2];
#pragma unroll
        for (int mi = 0; mi < 2; mi++) {
            uint32_t r = sAb + (uint32_t)(warp_m * 32 + mi * 16 + arow_l) * 80u
                             + (uint32_t)acol_l * 2u;
            ldm_x4(ah[mi], r);
            ldm_x4(al[mi], r + 32u);
        }
#pragma unroll
        for (int p = 0; p < 4; p++) {
            uint32_t t[4];
            uint32_t r = sBb + (uint32_t)(warp_n * 64 + p * 16 + brow_l) * 80u
                             + (uint32_t)bcol_l * 2u;
            ldm_x4(t, r);
            bb[2 * p][0] = t[0]; bb[2 * p][1] = t[1];
            bb[2 * p + 1][0] = t[2]; bb[2 * p + 1][1] = t[3];
        }
#pragma unroll
        for (int mi = 0; mi < 2; mi++)
#pragma unroll
            for (int ni = 0; ni < 8; ni++)
                mma_bf16(c[mi][ni], ah[mi], bb[ni]);
#pragma unroll
        for (int mi = 0; mi < 2; mi++)
#pragma unroll
            for (int ni = 0; ni < 8; ni++)
                mma_bf16(c[mi][ni], al[mi], bb[ni]);
#pragma unroll
        for (int p = 0; p < 4; p++) {
            uint32_t t[4];
            uint32_t r = sBb + (uint32_t)(warp_n * 64 + p * 16 + brow_l) * 80u
                             + (uint32_t)bcol_l * 2u + 32u;
            ldm_x4(t, r);
            bb[2 * p][0] = t[0]; bb[2 * p][1] = t[1];
            bb[2 * p + 1][0] = t[2]; bb[2 * p + 1][1] = t[3];
        }
#pragma unroll
        for (int mi = 0; mi < 2; mi++)
#pragma unroll
            for (int ni = 0; ni < 8; ni++)
                mma_bf16(c[mi][ni], ah[mi], bb[ni]);
        __syncthreads();
    }

    if (ATT) {
        if (tid < 128) { s_as[tid] = 0.f; s_ad[tid] = 0.f; }
        __syncthreads();
    }

    float ssv[2][2] = {{0.f, 0.f}, {0.f, 0.f}};
    float sdv[2][2] = {{0.f, 0.f}, {0.f, 0.f}};

#pragma unroll
    for (int ni = 0; ni < 8; ni++) {
        const int cA = col0 + warp_n * 64 + ni * 8 + tig * 2;
        float b0 = 0.f, b1 = 0.f;
        if (bias) { b0 = __ldg(&bias[cA]); b1 = __ldg(&bias[cA + 1]); }
        float asA = 0.f, asB = 0.f, adA = 0.f, adB = 0.f;
        if (ATT) {
            asA = __ldg(&a_s[cA]); asB = __ldg(&a_s[cA + 1]);
            adA = __ldg(&a_d[cA]); adB = __ldg(&a_d[cA + 1]);
        }
#pragma unroll
        for (int mi = 0; mi < 2; mi++) {
            const int r0g = row0 + warp_m * 32 + mi * 16 + g;
            const int r1g = r0g + 8;
            float v00 = c[mi][ni][0] + b0, v01 = c[mi][ni][1] + b1;
            float v10 = c[mi][ni][2] + b0, v11 = c[mi][ni][3] + b1;
            if (ACT == 1) {
                v00 = fmaxf(v00, 0.f); v01 = fmaxf(v01, 0.f);
                v10 = fmaxf(v10, 0.f); v11 = fmaxf(v11, 0.f);
            }
            if (ATT) {
                ssv[mi][0] += v00 * asA + v01 * asB;
                ssv[mi][1] += v10 * asA + v11 * asB;
                sdv[mi][0] += v00 * adA + v01 * adB;
                sdv[mi][1] += v10 * adA + v11 * adB;
            }
            if (Cf) {
                *(float2*)&Cf[(size_t)r0g * Nn + cA] = make_float2(v00, v01);
                *(float2*)&Cf[(size_t)r1g * Nn + cA] = make_float2(v10, v11);
            }
            if (Ch) {
                *(__half2*)&Ch[(size_t)r0g * Nn + cA] = __floats2half2_rn(v00, v01);
                *(__half2*)&Ch[(size_t)r1g * Nn + cA] = __floats2half2_rn(v10, v11);
            }
        }
    }

    if (ATT) {
#pragma unroll
        for (int mi = 0; mi < 2; mi++) {
            const int rl0 = warp_m * 32 + mi * 16 + g;
            atomicAdd(&s_as[rl0], ssv[mi][0]);
            atomicAdd(&s_as[rl0 + 8], ssv[mi][1]);
            atomicAdd(&s_ad[rl0], sdv[mi][0]);
            atomicAdd(&s_ad[rl0 + 8], sdv[mi][1]);
        }
        __syncthreads();
        if (tid < 128) {
            const int head = (ATT == 2) ? (int)blockIdx.x : 0;
            const int row = row0 + tid;
            atts[row * heads + head] = s_as[tid];
            attd[row * heads + head] = s_ad[tid];
        }
    }
}

// ================= fused node MLP: t -> u -> xo -> PQ =================
// K = 128 in all stages; A held in smem split-chunk layout between stages.
template <int AFROM>
__device__ __forceinline__ void gemm_stage(
    float (&c)[2][8][4],
    const bf16* Agb, const bf16* Bgb,
    uint32_t aChunkBase, uint32_t sAs, uint32_t sBs, uint32_t soff,
    int warp_m, int warp_n, int arow_l, int acol_l, int brow_l, int bcol_l)
{
#pragma unroll
    for (int i = 0; i < 2; i++)
#pragma unroll
        for (int j = 0; j < 8; j++)
#pragma unroll
            for (int q = 0; q < 4; q++) c[i][j][q] = 0.f;

    if (AFROM == 0) { cp_async16(sAs + soff, Agb); cp_async16(sAs + soff + 16, Agb + 8); }
    cp_async16(sBs + soff, Bgb);
    cp_async16(sBs + soff + 16, Bgb + 8);
    asm volatile("cp.async.commit_group;" ::: "memory");

#pragma unroll
    for (int kt = 0; kt < 8; kt++) {
        const int buf = kt & 1;
        if (kt + 1 < 8) {
            const int koff = (kt + 1) * 16;
            const uint32_t bofs = ((kt + 1) & 1) ? 10240u : 0u;
            if (AFROM == 0) {
                cp_async16(sAs + bofs + soff, Agb + koff);
                cp_async16(sAs + bofs + soff + 16, Agb + koff + 8);
            }
            cp_async16(sBs + bofs + soff, Bgb + koff);
            cp_async16(sBs + bofs + soff + 16, Bgb + koff + 8);
            asm volatile("cp.async.commit_group;" ::: "memory");
            asm volatile("cp.async.wait_group 1;" ::: "memory");
        } else {
            asm volatile("cp.async.wait_group 0;" ::: "memory");
        }
        __syncthreads();
        const uint32_t aBase = (AFROM == 0) ? (sAs + (uint32_t)buf * 10240u)
                                            : (aChunkBase + (uint32_t)kt * 10240u);
        const uint32_t bBase = sBs + (uint32_t)buf * 10240u;

        uint32_t ah[2][4], al[2][4], bb[8][2];
#pragma unroll
        for (int mi = 0; mi < 2; mi++) {
            uint32_t r = aBase + (uint32_t)(warp_m * 32 + mi * 16 + arow_l) * 80u
                               + (uint32_t)acol_l * 2u;
            ldm_x4(ah[mi], r);
            ldm_x4(al[mi], r + 32u);
        }
#pragma unroll
        for (int p = 0; p < 4; p++) {
            uint32_t t[4];
            uint32_t r = bBase + (uint32_t)(warp_n * 64 + p * 16 + brow_l) * 80u
                               + (uint32_t)bcol_l * 2u;
            ldm_x4(t, r);
            bb[2 * p][0] = t[0]; bb[2 * p][1] = t[1];
            bb[2 * p + 1][0] = t[2]; bb[2 * p + 1][1] = t[3];
        }
#pragma unroll
        for (int mi = 0; mi < 2; mi++)
#pragma unroll
            for (int ni = 0; ni < 8; ni++)
                mma_bf16(c[mi][ni], ah[mi], bb[ni]);
#pragma unroll
        for (int mi = 0; mi < 2; mi++)
#pragma unroll
            for (int ni = 0; ni < 8; ni++)
                mma_bf16(c[mi][ni], al[mi], bb[ni]);
#pragma unroll
        for (int p = 0; p < 4; p++) {
            uint32_t t[4];
            uint32_t r = bBase + (uint32_t)(warp_n * 64 + p * 16 + brow_l) * 80u
                               + (uint32_t)bcol_l * 2u + 32u;
            ldm_x4(t, r);
            bb[2 * p][0] = t[0]; bb[2 * p][1] = t[1];
            bb[2 * p + 1][0] = t[2]; bb[2 * p + 1][1] = t[3];
        }
#pragma unroll
        for (int mi = 0; mi < 2; mi++)
#pragma unroll
            for (int ni = 0; ni < 8; ni++)
                mma_bf16(c[mi][ni], ah[mi], bb[ni]);
        __syncthreads();
    }
}

__device__ __forceinline__ void store_split(char* base, int row, int col, float v0, float v1) {
    bf16 h0, l0, h1, l1;
    split_bf16(v0, h0, l0);
    split_bf16(v1, h1, l1);
    char* p = base + (col >> 4) * 10240 + row * 80 + (col & 15) * 2;
    __nv_bfloat162 hp, lp;
    hp.x = h0; hp.y = h1; lp.x = l0; lp.y = l1;
    *(__nv_bfloat162*)p = hp;
    *(__nv_bfloat162*)(p + 32) = lp;
}

__global__ void __launch_bounds__(256) k_nodeMLP(const float* __restrict__ bo1,
                                                 const float* __restrict__ bo2,
                                                 float* __restrict__ xo,
                                                 __half* __restrict__ PQh) {
    extern __shared__ char dyn[];
    char* uspC = dyn;                       // 8 chunks x 10240
    char* xspC = dyn + 81920;               // 8 chunks x 10240
    const uint32_t dynu = smem_u32(dyn);
    const uint32_t uspU = dynu;
    const uint32_t xspU = dynu + 81920u;
    const uint32_t sAs  = dynu + 163840u;   // 2 x 10240
    const uint32_t sBs  = dynu + 184320u;   // 2 x 10240

    const int tid = threadIdx.x;
    const int wid = tid >> 5, lane = tid & 31;
    const int g = lane >> 2, tig = lane & 3;
    const int warp_m = wid & 3, warp_n = wid >> 2;
    const int row0 = blockIdx.y * 128;
    const int lrow = tid >> 1, lsel = tid & 1;
    const uint32_t soff = (uint32_t)lrow * 80u + (uint32_t)lsel * 32u;
    const int arow_l = (((lane >> 3) & 1) << 3) + (lane & 7);
    const int acol_l = (lane >> 4) << 3;
    const int brow_l = (lane & 7) + ((lane >> 4) << 3);
    const int bcol_l = ((lane >> 3) & 1) << 3;

    float c[2][8][4];

    // ---- stage 1: u = relu(t @ Wo1 + bo1) -> usp
    {
        const bf16* Agb = g_tp + (size_t)(row0 + lrow) * 256 + lsel * 128;
        const bf16* Bgb = g_Wo1t + (size_t)lrow * 256 + lsel * 128;
        gemm_stage<0>(c, Agb, Bgb, 0u, sAs, sBs, soff,
                      warp_m, warp_n, arow_l, acol_l, brow_l, bcol_l);
#pragma unroll
        for (int ni = 0; ni < 8; ni++) {
            const int col = warp_n * 64 + ni * 8 + tig * 2;
            const float b0 = __ldg(&bo1[col]), b1 = __ldg(&bo1[col + 1]);
#pragma unroll
            for (int mi = 0; mi < 2; mi++) {
                const int r0l = warp_m * 32 + mi * 16 + g;
                store_split(uspC, r0l, col,
                            fmaxf(c[mi][ni][0] + b0, 0.f), fmaxf(c[mi][ni][1] + b1, 0.f));
                store_split(uspC, r0l + 8, col,
                            fmaxf(c[mi][ni][2] + b0, 0.f), fmaxf(c[mi][ni][3] + b1, 0.f));
            }
        }
        __syncthreads();
    }

    // ---- stage 2: xo = u @ Wo2 + bo2 -> global + xsp
    {
        const bf16* Bgb = g_Wo2t + (size_t)lrow * 256 + lsel * 128;
        gemm_stage<1>(c, nullptr, Bgb, uspU, sAs, sBs, soff,
                      warp_m, warp_n, arow_l, acol_l, brow_l, bcol_l);
#pragma unroll
        for (int ni = 0; ni < 8; ni++) {
            const int col = warp_n * 64 + ni * 8 + tig * 2;
            const float b0 = __ldg(&bo2[col]), b1 = __ldg(&bo2[col + 1]);
#pragma unroll
            for (int mi = 0; mi < 2; mi++) {
                const int r0l = warp_m * 32 + mi * 16 + g;
                const int r1l = r0l + 8;
                float v00 = c[mi][ni][0] + b0, v01 = c[mi][ni][1] + b1;
                float v10 = c[mi][ni][2] + b0, v11 = c[mi][ni][3] + b1;
                *(float2*)&xo[(size_t)(row0 + r0l) * 128 + col] = make_float2(v00, v01);
                *(float2*)&xo[(size_t)(row0 + r1l) * 128 + col] = make_float2(v10, v11);
                store_split(xspC, r0l, col, v00, v01);
                store_split(xspC, r1l, col, v10, v11);
            }
        }
        __syncthreads();
    }

    // ---- stage 3: PQ = xo @ WePQ + bePQ -> global (fp16), two 128-col passes
#pragma unroll
    for (int p = 0; p < 2; p++) {
        const bf16* Bgb = g_WePQt + (size_t)(p * 128 + lrow) * 256 + lsel * 128;
        gemm_stage<1>(c, nullptr, Bgb, xspU, sAs, sBs, soff,
                      warp_m, warp_n, arow_l, acol_l, brow_l, bcol_l);
#pragma unroll
        for (int ni = 0; ni < 8; ni++) {
            const int col = warp_n * 64 + ni * 8 + tig * 2;
            const int gcol = p * 128 + col;
            const float b0 = g_bePQ[gcol], b1 = g_bePQ[gcol + 1];
#pragma unroll
            for (int mi = 0; mi < 2; mi++) {
                const int r0g = row0 + warp_m * 32 + mi * 16 + g;
                const int r1g = r0g + 8;
                *(__half2*)&PQh[(size_t)r0g * 256 + gcol] =
                    __floats2half2_rn(c[mi][ni][0] + b0, c[mi][ni][1] + b1);
                *(__half2*)&PQh[(size_t)r1g * 256 + gcol] =
                    __floats2half2_rn(c[mi][ni][2] + b0, c[mi][ni][3] + b1);
            }
        }
    }
}

// ================= layer-1 aggregation (one-pass) =================
__global__ void __launch_bounds__(128) k_agg1(const float* __restrict__ b1) {
    const int n = blockIdx.x, tid = threadIdx.x;
    const int h = tid >> 5;
    const int beg = g_off[n], end = g_off[n + 1];

    __shared__ float s_ex[128 * 4];
    __shared__ int   s_s[128];

    const float4 ad = *(const float4*)&g_att1d[n * 4];

    float4 acc = make_float4(0.f, 0.f, 0.f, 0.f);
    float den = 0.f;
    for (int c0 = beg; c0 < end; c0 += 128) {
        int mcnt = min(128, end - c0);
        if (tid < mcnt) {
            int s = g_csrc[c0 + tid];
            s_s[tid] = s;
            float4 as = *(const float4*)&g_att1s[s * 4];
            s_ex[tid * 4 + 0] = expf(lrelu02(as.x + ad.x));
            s_ex[tid * 4 + 1] = expf(lrelu02(as.y + ad.y));
            s_ex[tid * 4 + 2] = expf(lrelu02(as.z + ad.z));
            s_ex[tid * 4 + 3] = expf(lrelu02(as.w + ad.w));
        }
        __syncthreads();
        for (int j = 0; j < mcnt; j++) {
            float w = s_ex[j * 4 + h];
            den += w;
            uint2 hv2 = *(const uint2*)&g_h1h[(size_t)s_s[j] * 512 + tid * 4];
            float2 f01 = __half22float2(*(const __half2*)&hv2.x);
            float2 f23 = __half22float2(*(const __half2*)&hv2.y);
            acc.x += f01.x * w; acc.y += f01.y * w;
            acc.z += f23.x * w; acc.w += f23.y * w;
        }
        __syncthreads();
    }
    const float invden = 1.f / den;
    float4 bv = *(const float4*)&b1[tid * 4];
    float o0 = eluf(acc.x * invden + bv.x), o1 = eluf(acc.y * invden + bv.y);
    float o2 = eluf(acc.z * invden + bv.z), o3 = eluf(acc.w * invden + bv.w);
    bf16 h0, l0, h1b, l1, h2b, l2, h3b, l3;
    split_bf16(o0, h0, l0); split_bf16(o1, h1b, l1);
    split_bf16(o2, h2b, l2); split_bf16(o3, h3b, l3);
    __nv_bfloat162 hA, hB, lA, lB;
    hA.x = h0; hA.y = h1b; hB.x = h2b; hB.y = h3b;
    lA.x = l0; lA.y = l1;  lB.x = l2;  lB.y = l3;
    const size_t rb = (size_t)n * 1024;
    const int cb = tid * 4;
    *(__nv_bfloat162*)&g_e1p[rb + cb]           = hA;
    *(__nv_bfloat162*)&g_e1p[rb + cb + 2]       = hB;
    *(__nv_bfloat162*)&g_e1p[rb + 512 + cb]     = lA;
    *(__nv_bfloat162*)&g_e1p[rb + 512 + cb + 2] = lB;
}

// ================= layer-2 aggregation (one-pass) =================
__global__ void __launch_bounds__(128) k_agg2(const float* __restrict__ b2) {
    const int n = blockIdx.x, tid = threadIdx.x;
    const int beg = g_off[n], end = g_off[n + 1];

    __shared__ float s_ex[128];
    __shared__ int   s_s[128];

    const float adn = g_att2d[n];

    float acc = 0.f, den = 0.f;
    for (int c0 = beg; c0 < end; c0 += 128) {
        int mcnt = min(128, end - c0);
        if (tid < mcnt) {
            int s = g_csrc[c0 + tid];
            s_s[tid] = s;
            s_ex[tid] = expf(lrelu02(g_att2s[s] + adn));
        }
        __syncthreads();
        for (int j = 0; j < mcnt; j++) {
            float w = s_ex[j];
            den += w;
            acc += __half2float(g_h2h[(size_t)s_s[j] * 128 + tid]) * w;
        }
        __syncthreads();
    }
    float o = eluf(acc / den + b2[tid]);
    bf16 h, l;
    split_bf16(o, h, l);
    g_tp[(size_t)n * 256 + tid]       = h;
    g_tp[(size_t)n * 256 + 128 + tid] = l;
}

// ================= fused edge MLP =================
__global__ void __launch_bounds__(256) k_edge_final(const void* __restrict__ ei,
                                                    const float* __restrict__ eattr,
                                                    const float* __restrict__ We1,
                                                    const float* __restrict__ We2,
                                                    const float* __restrict__ be2,
                                                    float* __restrict__ out) {
    __shared__ float sW1[16 * 128];
    __shared__ float sW2[128 * 16];
    __shared__ float sHid[8][128];
    const int tid = threadIdx.x;
    for (int i = tid; i < 2048; i += 256) {
        sW1[i] = We1[256 * 128 + i];
        sW2[i] = We2[i];
    }
    const int is64 = g_is64;
    __syncthreads();

    const int warp = tid >> 5, lane = tid & 31;
    const long e = (long)blockIdx.x * 8 + warp;
    if (e < EE) {
        int s = idx_at(ei, e, is64);
        int d = idx_at(ei, (long)EE + e, is64);
        uint2 pv = *(const uint2*)&g_PQh[(size_t)s * 256 + lane * 4];
        uint2 qv = *(const uint2*)&g_PQh[(size_t)d * 256 + 128 + lane * 4];
        float2 pa = __half22float2(*(const __half2*)&pv.x);
        float2 pb = __half22float2(*(const __half2*)&pv.y);
        float2 qa = __half22float2(*(const __half2*)&qv.x);
        float2 qb = __half22float2(*(const __half2*)&qv.y);
        float4 hv;
        hv.x = pa.x + qa.x; hv.y = pa.y + qa.y;
        hv.z = pb.x + qb.x; hv.w = pb.y + qb.y;
        float eav = (lane < 16) ? eattr[e * 16 + lane] : 0.f;
#pragma unroll
        for (int k = 0; k < 16; k++) {
            float ek = __shfl_sync(0xffffffffu, eav, k);
            float4 wv = *(const float4*)&sW1[k * 128 + lane * 4];
            hv.x += ek * wv.x; hv.y += ek * wv.y;
            hv.z += ek * wv.z; hv.w += ek * wv.w;
        }
        hv.x = fmaxf(hv.x, 0.f); hv.y = fmaxf(hv.y, 0.f);
        hv.z = fmaxf(hv.z, 0.f); hv.w = fmaxf(hv.w, 0.f);
        *(float4*)&sHid[warp][lane * 4] = hv;
    }
    __syncwarp();
    if (e < EE) {
        const int o = lane & 15, half = lane >> 4;
        float acc = 0.f;
#pragma unroll
        for (int c = 0; c < 64; c++) {
            int cc = half + 2 * c;
            acc += sHid[warp][cc] * sW2[cc * 16 + o];
        }
        acc += __shfl_xor_sync(0xffffffffu, acc, 16);
        if (lane < 16) out[e * 16 + lane] = acc + be2[lane];
    }
}

// ================= launcher =================
extern "C" void kernel_launch(void* const* d_in, const int* in_sizes, int n_in,
                              void* d_out, int out_size) {
    const float* x    = (const float*)d_in[0];
    const void*  ei   = d_in[1];
    const float* eatt = (const float*)d_in[2];
    const float* W1   = (const float*)d_in[3];
    const float* as1  = (const float*)d_in[4];
    const float* ad1  = (const float*)d_in[5];
    const float* b1   = (const float*)d_in[6];
    const float* W2   = (const float*)d_in[7];
    const float* as2  = (const float*)d_in[8];
    const float* ad2  = (const float*)d_in[9];
    const float* b2   = (const float*)d_in[10];
    const float* Wo1  = (const float*)d_in[11];
    const float* bo1  = (const float*)d_in[12];
    const float* Wo2  = (const float*)d_in[13];
    const float* bo2  = (const float*)d_in[14];
    const float* We1  = (const float*)d_in[15];
    const float* be1  = (const float*)d_in[16];
    const float* We2  = (const float*)d_in[17];
    const float* be2  = (const float*)d_in[18];

    float* out  = (float*)d_out;
    float* xo   = out;
    float* eout = out + (size_t)NN * 128;

    bf16 *xp, *e1p, *W1t, *W2t;
    __half *h1h, *h2h, *PQh;
    float *a1s, *a1d, *a2s, *a2d;
    cudaGetSymbolAddress((void**)&xp,  g_xp);
    cudaGetSymbolAddress((void**)&e1p, g_e1p);
    cudaGetSymbolAddress((void**)&W1t, g_W1t);
    cudaGetSymbolAddress((void**)&W2t, g_W2t);
    cudaGetSymbolAddress((void**)&h1h, g_h1h);
    cudaGetSymbolAddress((void**)&h2h, g_h2h);
    cudaGetSymbolAddress((void**)&PQh, g_PQh);
    cudaGetSymbolAddress((void**)&a1s, g_att1s);
    cudaGetSymbolAddress((void**)&a1d, g_att1d);
    cudaGetSymbolAddress((void**)&a2s, g_att2s);
    cudaGetSymbolAddress((void**)&a2d, g_att2d);

    cudaFuncSetAttribute(k_nodeMLP, cudaFuncAttributeMaxDynamicSharedMemorySize, 204800);

    // conversions first, then gemm1 at launch slot 4 (ncu profiles it)
    k_convA<<<(int)(((long)NN * 128 + 255) / 256), 256>>>(x, xp, 128, (long)NN * 128);
    k_convWall<<<770, 256>>>(W1, W2, Wo1, Wo2, We1, be1);
    k_init<<<125, 256>>>((const int*)ei);
    k_mgemm<0, 2><<<dim3(4, 250), 256>>>(xp, W1t, 128, 512,
        nullptr, nullptr, h1h, as1, ad1, a1s, a1d, 4);

    // CSR build
    k_hist<<<(ET + 255) / 256, 256>>>(ei);
    k_scan1<<<125, 256>>>();
    k_scan2<<<1, 128>>>();
    k_scan3<<<125, 256>>>();
    k_scatter<<<(ET + 255) / 256, 256>>>(ei);

    // layer 1 aggregate
    k_agg1<<<NN, 128>>>(b1);

    // layer 2
    k_mgemm<0, 1><<<dim3(1, 250), 256>>>(e1p, W2t, 512, 128,
        nullptr, nullptr, h2h, as2, ad2, a2s, a2d, 1);
    k_agg2<<<NN, 128>>>(b2);

    // fused node MLP (t -> u -> xo -> PQ)
    k_nodeMLP<<<dim3(1, 250), 256, 204800>>>(bo1, bo2, xo, PQh);

    // edge MLP
    k_edge_final<<<EE / 8, 256>>>(ei, eatt, We1, We2, be2, eout);
}